// round 5
// baseline (speedup 1.0000x reference)
#include <cuda_runtime.h>
#include <math.h>
#include <stdint.h>

#define BATCH   1024
#define NKPS    24
#define NEDGE   552
#define M_NODE  (BATCH*NKPS)    // 24576
#define M_EDGE  (BATCH*NEDGE)   // 565248
#define BN_EPS  1e-5f

// ---------------- scratch (device globals) ---------------------------------
__device__ float g_bufA[(size_t)M_EDGE*128];   // h2 (x_skip), tf32-rounded
__device__ float g_bufB[(size_t)M_EDGE*128];   // h4, full fp32
__device__ float g_n1 [(size_t)M_NODE*128];    // h1, tf32-rounded
__device__ float g_n2 [(size_t)M_NODE*128];    // node2 (rounded) / node4 (fp32)
__device__ float g_n3 [(size_t)M_NODE*128];    // h3, tf32-rounded
__device__ float g_w1e[384*128];               // folded+rounded layer-1 weights
__device__ float g_w2e[128*128];               // rounded layer-2 weights
__device__ float g_beff[128];                  // folded layer-1 bias (fp32)
__device__ float g_psum[(M_EDGE/128)*128];
__device__ float g_psq [(M_EDGE/128)*128];
__device__ float g_s[4*128];
__device__ float g_t[4*128];

// ---------------- small helpers ---------------------------------------------
__device__ __forceinline__ uint32_t smem_u32(const void* p) {
    uint32_t a;
    asm("{ .reg .u64 t; cvta.to.shared.u64 t, %1; cvt.u32.u64 %0, t; }" : "=r"(a) : "l"(p));
    return a;
}
__device__ __forceinline__ void cp16(uint32_t dst, const void* src) {
    asm volatile("cp.async.cg.shared.global [%0], [%1], 16;" :: "r"(dst), "l"(src));
}
__device__ __forceinline__ uint32_t f2tf(float x) {
    uint32_t u;
    asm("cvt.rna.tf32.f32 %0, %1;" : "=r"(u) : "f"(x));
    return u;
}
__device__ __forceinline__ void mma8(float d[4],
                                     uint32_t a0, uint32_t a1, uint32_t a2, uint32_t a3,
                                     uint32_t b0, uint32_t b1) {
    asm volatile("mma.sync.aligned.m16n8k8.row.col.f32.tf32.tf32.f32 "
        "{%0,%1,%2,%3}, {%4,%5,%6,%7}, {%8,%9}, {%0,%1,%2,%3};"
        : "+f"(d[0]), "+f"(d[1]), "+f"(d[2]), "+f"(d[3])
        : "r"(a0), "r"(a1), "r"(a2), "r"(a3), "r"(b0), "r"(b1));
}

// ---------------- SMEM layout (bytes) ----------------------------------------
// chunk buffers: [128 rows][20-float stride] = 10240B each, 2 A + 2 W
// A2: [128][132-float stride] = 67584B
#define OFF_RECV   0
#define OFF_SEND   512
#define OFF_BE     1024
#define OFF_B2V    1536
#define OFF_CHA    2048                 /* 2 x 10240 */
#define OFF_CHW    22528                /* 2 x 10240 */
#define OFF_A2     43008                /* 67584 */
#define SMEM_TOTAL 110592

// ---------------- fused 2-layer MLP, mma.sync tf32 ---------------------------
// MODE 1: stage-1 special: A = raw inputs [M][6], W1/W2 raw (rounded inline)
// MODE 0: A plain [M][K1PAD], pre-rounded
// MODE 2: edge gather K1=256 (recv|send rows of A[M_NODE][128]), pre-rounded
// MODE 3: edge gather K1=384 (recv|send of A + skip rows of Askip), pre-rounded
template<int MODE, int K1PAD, bool ROUND_OUT, bool CVT_B2>
__global__ __launch_bounds__(256, 2)
void mlp2(const float* __restrict__ A, const float* __restrict__ Askip,
          const float* __restrict__ W1e, const float* __restrict__ beff,
          const float* __restrict__ W2e, const float* __restrict__ b2,
          float* __restrict__ out,
          float* __restrict__ psum, float* __restrict__ psq)
{
    extern __shared__ char smem[];
    float* smf = (float*)smem;
    const uint32_t sb = smem_u32(smem);
    const int tid = threadIdx.x;
    const int wid = tid >> 5, lid = tid & 31;
    const int g = lid >> 2, tg = lid & 3;
    const int wm = wid & 3, wn = wid >> 2;       // warp tile: rows wm*32, cols wn*64
    const int row0 = blockIdx.x * 128;
    int* rs = (int*)(smem + OFF_RECV);
    int* ss = (int*)(smem + OFF_SEND);

    if ((MODE == 2 || MODE == 3) && tid < 128) {
        int row = row0 + tid;
        int b = row / NEDGE;
        int e = row - b * NEDGE;
        int r = e / 23;
        int j = e - r * 23;
        int s = j + (j >= r);
        rs[tid] = b * NKPS + r;
        ss[tid] = b * NKPS + s;
    }
    if (tid < 128) {
        smf[OFF_BE/4  + tid] = beff[tid];
        smf[OFF_B2V/4 + tid] = b2[tid];
    }
    __syncthreads();

    float acc[2][8][4];
#pragma unroll
    for (int f = 0; f < 2; f++)
#pragma unroll
        for (int nt = 0; nt < 8; nt++)
#pragma unroll
            for (int q = 0; q < 4; q++) acc[f][nt][q] = 0.f;

    // ================= LAYER 1 =================
    if (MODE == 1) {
        // inline fill: pad K 6->16, round to tf32
#pragma unroll
        for (int i = 0; i < 8; i++) {
            int idx = i * 256 + tid;              // 2048 elems
            int row = idx >> 4, col = idx & 15;
            float av = (col < 6) ? A[(size_t)(row0 + row) * 6 + col] : 0.f;
            float wv = (col < 6) ? W1e[row * 6 + col] : 0.f;   // W1 raw [128][6]
            smf[OFF_CHA/4 + row * 20 + col] = __uint_as_float(f2tf(av));
            smf[OFF_CHW/4 + row * 20 + col] = __uint_as_float(f2tf(wv));
        }
        __syncthreads();
        const uint32_t* As = (const uint32_t*)(smem + OFF_CHA);
        const uint32_t* Ws = (const uint32_t*)(smem + OFF_CHW);
#pragma unroll
        for (int ks = 0; ks < 2; ks++) {
            uint32_t a[2][4];
#pragma unroll
            for (int f = 0; f < 2; f++) {
                const uint32_t* p = As + (wm * 32 + f * 16 + g) * 20 + ks * 8 + tg;
                a[f][0] = p[0]; a[f][1] = p[8 * 20]; a[f][2] = p[4]; a[f][3] = p[8 * 20 + 4];
            }
#pragma unroll
            for (int nt = 0; nt < 8; nt++) {
                const uint32_t* q = Ws + (wn * 64 + nt * 8 + g) * 20 + ks * 8 + tg;
                uint32_t b0 = q[0], b1 = q[4];
                mma8(acc[0][nt], a[0][0], a[0][1], a[0][2], a[0][3], b0, b1);
                mma8(acc[1][nt], a[1][0], a[1][1], a[1][2], a[1][3], b0, b1);
            }
        }
        __syncthreads();
    } else {
        constexpr int NCH = K1PAD / 16;
        auto issue_chunk = [&](int c, int buf) {
            const int kb = c * 16;
#pragma unroll
            for (int i = 0; i < 2; i++) {
                int idx4 = i * 256 + tid;          // 512 float4
                int row = idx4 >> 2, c4 = idx4 & 3;
                int kk = kb + c4 * 4;
                const float* src;
                if (MODE == 0) {
                    src = A + (size_t)(row0 + row) * K1PAD + kk;
                } else {
                    if (kk < 128)      src = A + (size_t)rs[row] * 128 + kk;
                    else if (kk < 256) src = A + (size_t)ss[row] * 128 + (kk - 128);
                    else               src = Askip + (size_t)(row0 + row) * 128 + (kk - 256);
                }
                cp16(sb + OFF_CHA + buf * 10240 + row * 80 + c4 * 16, src);
                cp16(sb + OFF_CHW + buf * 10240 + row * 80 + c4 * 16,
                     W1e + (size_t)row * K1PAD + kk);
            }
            asm volatile("cp.async.commit_group;");
        };
        issue_chunk(0, 0);
        if (NCH > 1) issue_chunk(1, 1);
        for (int c = 0; c < NCH; c++) {
            const int buf = c & 1;
            if (c + 1 < NCH) asm volatile("cp.async.wait_group 1;");
            else             asm volatile("cp.async.wait_group 0;");
            __syncthreads();
            const uint32_t* As = (const uint32_t*)(smem + OFF_CHA + buf * 10240);
            const uint32_t* Ws = (const uint32_t*)(smem + OFF_CHW + buf * 10240);
#pragma unroll
            for (int ks = 0; ks < 2; ks++) {
                uint32_t a[2][4];
#pragma unroll
                for (int f = 0; f < 2; f++) {
                    const uint32_t* p = As + (wm * 32 + f * 16 + g) * 20 + ks * 8 + tg;
                    a[f][0] = p[0]; a[f][1] = p[8 * 20]; a[f][2] = p[4]; a[f][3] = p[8 * 20 + 4];
                }
#pragma unroll
                for (int nt = 0; nt < 8; nt++) {
                    const uint32_t* q = Ws + (wn * 64 + nt * 8 + g) * 20 + ks * 8 + tg;
                    uint32_t b0 = q[0], b1 = q[4];
                    mma8(acc[0][nt], a[0][0], a[0][1], a[0][2], a[0][3], b0, b1);
                    mma8(acc[1][nt], a[1][0], a[1][1], a[1][2], a[1][3], b0, b1);
                }
            }
            __syncthreads();
            if (c + 2 < NCH) issue_chunk(c + 2, buf);
        }
    }

    // ---- prefetch W2 chunks 0,1 (overlap with epilogue 1) ----
    auto issue_w2 = [&](int c, int buf) {
#pragma unroll
        for (int i = 0; i < 2; i++) {
            int idx4 = i * 256 + tid;
            int row = idx4 >> 2, c4 = idx4 & 3;
            int kk = c * 16 + c4 * 4;
            cp16(sb + OFF_CHW + buf * 10240 + row * 80 + c4 * 16,
                 W2e + (size_t)row * 128 + kk);
        }
        asm volatile("cp.async.commit_group;");
    };
    issue_w2(0, 0);
    issue_w2(1, 1);

    // ---- epilogue 1: bias + ELU -> A2 (tf32-rounded), reset acc ----
    {
        float* A2 = smf + OFF_A2 / 4;
#pragma unroll
        for (int f = 0; f < 2; f++) {
            int r = wm * 32 + f * 16 + g;
#pragma unroll
            for (int nt = 0; nt < 8; nt++) {
                int n0 = wn * 64 + nt * 8 + tg * 2;
                float be0 = smf[OFF_BE/4 + n0], be1 = smf[OFF_BE/4 + n0 + 1];
                float v0 = acc[f][nt][0] + be0;
                float v1 = acc[f][nt][1] + be1;
                float v2 = acc[f][nt][2] + be0;
                float v3 = acc[f][nt][3] + be1;
                v0 = (v0 > 0.f) ? v0 : expm1f(v0);
                v1 = (v1 > 0.f) ? v1 : expm1f(v1);
                v2 = (v2 > 0.f) ? v2 : expm1f(v2);
                v3 = (v3 > 0.f) ? v3 : expm1f(v3);
                *(float2*)(A2 + r * 132 + n0) =
                    make_float2(__uint_as_float(f2tf(v0)), __uint_as_float(f2tf(v1)));
                *(float2*)(A2 + (r + 8) * 132 + n0) =
                    make_float2(__uint_as_float(f2tf(v2)), __uint_as_float(f2tf(v3)));
#pragma unroll
                for (int q = 0; q < 4; q++) acc[f][nt][q] = 0.f;
            }
        }
    }
    __syncthreads();

    // ================= LAYER 2 (W2 streamed, A2 resident) =================
    for (int c = 0; c < 8; c++) {
        const int buf = c & 1;
        if (c < 7) asm volatile("cp.async.wait_group 1;");
        else       asm volatile("cp.async.wait_group 0;");
        __syncthreads();
        const uint32_t* As = (const uint32_t*)(smem + OFF_A2);
        const char* Wb = smem + OFF_CHW + buf * 10240;
#pragma unroll
        for (int ks = 0; ks < 2; ks++) {
            uint32_t a[2][4];
#pragma unroll
            for (int f = 0; f < 2; f++) {
                const uint32_t* p = As + (wm * 32 + f * 16 + g) * 132 + c * 16 + ks * 8 + tg;
                a[f][0] = p[0]; a[f][1] = p[8 * 132]; a[f][2] = p[4]; a[f][3] = p[8 * 132 + 4];
            }
#pragma unroll
            for (int nt = 0; nt < 8; nt++) {
                uint32_t b0, b1;
                if (CVT_B2) {
                    const float* q = (const float*)Wb + (wn * 64 + nt * 8 + g) * 20 + ks * 8 + tg;
                    b0 = f2tf(q[0]); b1 = f2tf(q[4]);
                } else {
                    const uint32_t* q = (const uint32_t*)Wb + (wn * 64 + nt * 8 + g) * 20 + ks * 8 + tg;
                    b0 = q[0]; b1 = q[4];
                }
                mma8(acc[0][nt], a[0][0], a[0][1], a[0][2], a[0][3], b0, b1);
                mma8(acc[1][nt], a[1][0], a[1][1], a[1][2], a[1][3], b0, b1);
            }
        }
        __syncthreads();
        if (c + 2 < 8) issue_w2(c + 2, buf);
    }

    // ---- epilogue 2: bias + ELU -> A2 staging, then store + stats ----
    {
        float* A2 = smf + OFF_A2 / 4;
#pragma unroll
        for (int f = 0; f < 2; f++) {
            int r = wm * 32 + f * 16 + g;
#pragma unroll
            for (int nt = 0; nt < 8; nt++) {
                int n0 = wn * 64 + nt * 8 + tg * 2;
                float be0 = smf[OFF_B2V/4 + n0], be1 = smf[OFF_B2V/4 + n0 + 1];
                float v0 = acc[f][nt][0] + be0;
                float v1 = acc[f][nt][1] + be1;
                float v2 = acc[f][nt][2] + be0;
                float v3 = acc[f][nt][3] + be1;
                v0 = (v0 > 0.f) ? v0 : expm1f(v0);
                v1 = (v1 > 0.f) ? v1 : expm1f(v1);
                v2 = (v2 > 0.f) ? v2 : expm1f(v2);
                v3 = (v3 > 0.f) ? v3 : expm1f(v3);
                if (ROUND_OUT) {
                    v0 = __uint_as_float(f2tf(v0));
                    v1 = __uint_as_float(f2tf(v1));
                    v2 = __uint_as_float(f2tf(v2));
                    v3 = __uint_as_float(f2tf(v3));
                }
                *(float2*)(A2 + r * 132 + n0)       = make_float2(v0, v1);
                *(float2*)(A2 + (r + 8) * 132 + n0) = make_float2(v2, v3);
            }
        }
    }
    __syncthreads();
    {
        const float* A2 = smf + OFF_A2 / 4;
#pragma unroll
        for (int i = 0; i < 16; i++) {
            int idx4 = i * 256 + tid;
            int row = idx4 >> 5, c4 = idx4 & 31;
            float4 v = *(const float4*)(A2 + row * 132 + c4 * 4);
            *(float4*)(out + (size_t)(row0 + row) * 128 + c4 * 4) = v;
        }
        if (tid < 128) {
            float S = 0.f, Q = 0.f;
#pragma unroll 8
            for (int r = 0; r < 128; r++) {
                float x = A2[r * 132 + tid];
                S += x;
                Q += x * x;
            }
            psum[(size_t)blockIdx.x * 128 + tid] = S;
            psq [(size_t)blockIdx.x * 128 + tid] = Q;
        }
    }
}

// ---------------- prep: fold BN affine into layer-1 weights, round both ------
// blocks 0..127: W1e[n][k] = round(W1[n][k]*s(k)); beff[n] = b1[n] + sum W1[n][k]*t(k)
// blocks 128..191: W2e = round(W2)
__global__ void prep(const float* __restrict__ W1, const float* __restrict__ b1,
                     int k1real, int K1PAD,
                     const float* __restrict__ sA, const float* __restrict__ tA,
                     const float* __restrict__ sB, const float* __restrict__ tB,
                     const float* __restrict__ W2,
                     float* __restrict__ W1e, float* __restrict__ beff,
                     float* __restrict__ W2e)
{
    const int tid = threadIdx.x;
    if (blockIdx.x < 128) {
        const int n = blockIdx.x;
        float partial = 0.f;
        for (int k = tid; k < K1PAD; k += 256) {
            float w = (k < k1real) ? W1[(size_t)n * k1real + k] : 0.f;
            float s = 1.f, t = 0.f;
            if (k < k1real) {
                if (k < 256) { if (sA) { s = sA[k & 127]; t = tA[k & 127]; } }
                else         { s = sB[k - 256]; t = tB[k - 256]; }
            }
            float u;
            asm("cvt.rna.tf32.f32 %0, %1;" : "=f"(u) : "f"(w * s));
            W1e[(size_t)n * K1PAD + k] = u;
            partial += w * t;
        }
        __shared__ float red[256];
        red[tid] = partial;
        __syncthreads();
        for (int off = 128; off; off >>= 1) {
            if (tid < off) red[tid] += red[tid + off];
            __syncthreads();
        }
        if (tid == 0) beff[n] = b1[n] + red[0];
    } else {
        int idx = (blockIdx.x - 128) * 256 + tid;
        float u;
        asm("cvt.rna.tf32.f32 %0, %1;" : "=f"(u) : "f"(W2[idx]));
        W2e[idx] = u;
    }
}

// ---------------- BN finalize (grid=1, 1024 threads, coalesced) --------------
__global__ void bn_finalize(const float* __restrict__ psum, const float* __restrict__ psq,
                            int nblocks, float Minv,
                            const float* __restrict__ g, const float* __restrict__ be,
                            float* __restrict__ s, float* __restrict__ t)
{
    const int tid = threadIdx.x;
    const int c = tid & 127, part = tid >> 7;   // 8 partitions
    float S = 0.f, Q = 0.f;
    for (int i = part; i < nblocks; i += 8) {
        S += psum[(size_t)i * 128 + c];
        Q += psq [(size_t)i * 128 + c];
    }
    __shared__ float sS[8][128], sQ[8][128];
    sS[part][c] = S;
    sQ[part][c] = Q;
    __syncthreads();
    if (tid < 128) {
        float St = 0.f, Qt = 0.f;
#pragma unroll
        for (int p = 0; p < 8; p++) { St += sS[p][tid]; Qt += sQ[p][tid]; }
        float mean = St * Minv;
        float var  = Qt * Minv - mean * mean;
        float inv  = rsqrtf(var + BN_EPS);
        float sv   = g[tid] * inv;
        s[tid] = sv;
        t[tid] = be[tid] - mean * sv;
    }
}

// ---------------- edge2node (optionally tf32-round output) -------------------
template<bool R>
__global__ void edge2node(const float* __restrict__ h,
                          const float* __restrict__ s, const float* __restrict__ t,
                          float* __restrict__ outn)
{
    int c  = threadIdx.x;
    int bn = blockIdx.x;
    const float* p = h + (size_t)bn * 23 * 128 + c;
    float acc = 0.f;
#pragma unroll
    for (int j = 0; j < 23; j++) acc += p[(size_t)j * 128];
    float val = (s[c] * acc + 23.f * t[c]) * (1.f / 24.f);
    if (R) val = __uint_as_float(f2tf(val));
    outn[(size_t)bn * 128 + c] = val;
}

// ---------------- final projection -------------------------------------------
__global__ void final_proj(const float* __restrict__ node4,
                           const float* __restrict__ fo_w, const float* __restrict__ fo_b,
                           float* __restrict__ out)
{
    int b = blockIdx.x;
    int c = threadIdx.x;
    float a0 = 0.f, a1 = 0.f;
#pragma unroll
    for (int n = 0; n < NKPS; n++) {
        float v = node4[((size_t)b * NKPS + n) * 128 + c];
        a0 = fmaf(v, fo_w[n * 128 + c],        a0);
        a1 = fmaf(v, fo_w[3072 + n * 128 + c], a1);
    }
    __shared__ float r0[128], r1[128];
    r0[c] = a0; r1[c] = a1;
    __syncthreads();
    for (int off = 64; off; off >>= 1) {
        if (c < off) { r0[c] += r0[c + off]; r1[c] += r1[c + off]; }
        __syncthreads();
    }
    if (c == 0) {
        out[b * 2 + 0] = r0[0] + fo_b[0];
        out[b * 2 + 1] = r1[0] + fo_b[1];
    }
}

// ---------------- launch ------------------------------------------------------
extern "C" void kernel_launch(void* const* d_in, const int* in_sizes, int n_in,
                              void* d_out, int out_size)
{
    const float* inputs = (const float*)d_in[0];
    const float* fo_w = (const float*)d_in[3];
    const float* fo_b = (const float*)d_in[4];
    const float* m1w1 = (const float*)d_in[5];
    const float* m1b1 = (const float*)d_in[6];
    const float* m1w2 = (const float*)d_in[7];
    const float* m1b2 = (const float*)d_in[8];
    const float* m1g  = (const float*)d_in[9];
    const float* m1be = (const float*)d_in[10];
    const float* m2w1 = (const float*)d_in[11];
    const float* m2b1 = (const float*)d_in[12];
    const float* m2w2 = (const float*)d_in[13];
    const float* m2b2 = (const float*)d_in[14];
    const float* m2g  = (const float*)d_in[15];
    const float* m2be = (const float*)d_in[16];
    const float* m3w1 = (const float*)d_in[17];
    const float* m3b1 = (const float*)d_in[18];
    const float* m3w2 = (const float*)d_in[19];
    const float* m3b2 = (const float*)d_in[20];
    const float* m3g  = (const float*)d_in[21];
    const float* m3be = (const float*)d_in[22];
    const float* m4w1 = (const float*)d_in[23];
    const float* m4b1 = (const float*)d_in[24];
    const float* m4w2 = (const float*)d_in[25];
    const float* m4b2 = (const float*)d_in[26];
    const float* m4g  = (const float*)d_in[27];
    const float* m4be = (const float*)d_in[28];
    float* out = (float*)d_out;

    float *bufA, *bufB, *n1, *n2, *n3, *w1e, *w2e, *beff, *psum, *psq, *sArr, *tArr;
    cudaGetSymbolAddress((void**)&bufA, g_bufA);
    cudaGetSymbolAddress((void**)&bufB, g_bufB);
    cudaGetSymbolAddress((void**)&n1,   g_n1);
    cudaGetSymbolAddress((void**)&n2,   g_n2);
    cudaGetSymbolAddress((void**)&n3,   g_n3);
    cudaGetSymbolAddress((void**)&w1e,  g_w1e);
    cudaGetSymbolAddress((void**)&w2e,  g_w2e);
    cudaGetSymbolAddress((void**)&beff, g_beff);
    cudaGetSymbolAddress((void**)&psum, g_psum);
    cudaGetSymbolAddress((void**)&psq,  g_psq);
    cudaGetSymbolAddress((void**)&sArr, g_s);
    cudaGetSymbolAddress((void**)&tArr, g_t);

    cudaFuncSetAttribute(mlp2<1,16,true,true>,   cudaFuncAttributeMaxDynamicSharedMemorySize, SMEM_TOTAL);
    cudaFuncSetAttribute(mlp2<2,256,true,false>, cudaFuncAttributeMaxDynamicSharedMemorySize, SMEM_TOTAL);
    cudaFuncSetAttribute(mlp2<0,128,true,false>, cudaFuncAttributeMaxDynamicSharedMemorySize, SMEM_TOTAL);
    cudaFuncSetAttribute(mlp2<3,384,false,false>,cudaFuncAttributeMaxDynamicSharedMemorySize, SMEM_TOTAL);

    const int GN = M_NODE / 128;   // 192
    const int GE = M_EDGE / 128;   // 4416
    const float MinvN = 1.0f / (float)M_NODE;
    const float MinvE = 1.0f / (float)M_EDGE;

    // stage 1 (nodes): inline-prep MLP (raw W, raw inputs), BN -> s/t[0]
    mlp2<1,16,true,true><<<GN, 256, SMEM_TOTAL>>>(inputs, nullptr, m1w1, m1b1,
                                                  m1w2, m1b2, n1, psum, psq);
    bn_finalize<<<1, 1024>>>(psum, psq, GN, MinvN, m1g, m1be, sArr + 0, tArr + 0);

    // stage 2 (edges): fold BN1, gathered fused MLP, BN -> s/t[1]
    prep<<<192, 256>>>(m2w1, m2b1, 256, 256, sArr + 0, tArr + 0, nullptr, nullptr,
                       m2w2, w1e, beff, w2e);
    mlp2<2,256,true,false><<<GE, 256, SMEM_TOTAL>>>(n1, nullptr, w1e, beff,
                                                    w2e, m2b2, bufA, psum, psq);
    bn_finalize<<<1, 1024>>>(psum, psq, GE, MinvE, m2g, m2be, sArr + 128, tArr + 128);

    edge2node<true><<<M_NODE, 128>>>(bufA, sArr + 128, tArr + 128, n2);

    // stage 3 (nodes)
    prep<<<192, 256>>>(m3w1, m3b1, 128, 128, nullptr, nullptr, nullptr, nullptr,
                       m3w2, w1e, beff, w2e);
    mlp2<0,128,true,false><<<GN, 256, SMEM_TOTAL>>>(n2, nullptr, w1e, beff,
                                                    w2e, m3b2, n3, psum, psq);
    bn_finalize<<<1, 1024>>>(psum, psq, GN, MinvN, m3g, m3be, sArr + 256, tArr + 256);

    // stage 4 (edges + skip): fold BN3 (k<256) + BN2 (skip)
    prep<<<192, 256>>>(m4w1, m4b1, 384, 384, sArr + 256, tArr + 256, sArr + 128, tArr + 128,
                       m4w2, w1e, beff, w2e);
    mlp2<3,384,false,false><<<GE, 256, SMEM_TOTAL>>>(n3, bufA, w1e, beff,
                                                     w2e, m4b2, bufB, psum, psq);
    bn_finalize<<<1, 1024>>>(psum, psq, GE, MinvE, m4g, m4be, sArr + 384, tArr + 384);

    edge2node<false><<<M_NODE, 128>>>(bufB, sArr + 384, tArr + 384, n2);
    final_proj<<<BATCH, 128>>>(n2, fo_w, fo_b, out);
}

// round 6
// speedup vs baseline: 1.2582x; 1.2582x over previous
#include <cuda_runtime.h>
#include <math.h>
#include <stdint.h>

#define BATCH   1024
#define NKPS    24
#define NEDGE   552
#define M_NODE  (BATCH*NKPS)    // 24576
#define M_EDGE  (BATCH*NEDGE)   // 565248
#define BN_EPS  1e-5f

// ---------------- scratch (device globals) ---------------------------------
__device__ float g_bufA[(size_t)M_EDGE*128];   // h2 (x_skip), tf32-rounded
__device__ float g_bufB[(size_t)M_EDGE*128];   // h4, fp32
__device__ float g_n1 [(size_t)M_NODE*128];    // h1 rounded
__device__ float g_n2 [(size_t)M_NODE*128];    // node2 (rounded) / node4 (fp32)
__device__ float g_n3 [(size_t)M_NODE*128];    // h3 rounded
__device__ float g_ps [(size_t)M_NODE*256];    // P|S per node, fp32
__device__ float g_psfrag[2*16384];            // P/S weight frags
__device__ float g_skipfrag[16384];            // stage4 skip weight frags
__device__ float g_w1frag[16384];              // stage3 layer1 frags
__device__ float g_l2frag[16384];              // current layer2 frags
__device__ float g_beff[128];
__device__ float g_psum[(M_EDGE/128)*128];
__device__ float g_psq [(M_EDGE/128)*128];
__device__ float g_s[4*128];
__device__ float g_t[4*128];

// ---------------- helpers ----------------------------------------------------
__device__ __forceinline__ uint32_t smem_u32(const void* p) {
    uint32_t a;
    asm("{ .reg .u64 t; cvta.to.shared.u64 t, %1; cvt.u32.u64 %0, t; }" : "=r"(a) : "l"(p));
    return a;
}
__device__ __forceinline__ void cp16(uint32_t dst, const void* src) {
    asm volatile("cp.async.cg.shared.global [%0], [%1], 16;" :: "r"(dst), "l"(src));
}
__device__ __forceinline__ uint32_t f2tf(float x) {
    uint32_t u;
    asm("cvt.rna.tf32.f32 %0, %1;" : "=r"(u) : "f"(x));
    return u;
}
__device__ __forceinline__ float rtf(float x) { return __uint_as_float(f2tf(x)); }
__device__ __forceinline__ void mma8(float d[4],
                                     uint32_t a0, uint32_t a1, uint32_t a2, uint32_t a3,
                                     uint32_t b0, uint32_t b1) {
    asm volatile("mma.sync.aligned.m16n8k8.row.col.f32.tf32.tf32.f32 "
        "{%0,%1,%2,%3}, {%4,%5,%6,%7}, {%8,%9}, {%0,%1,%2,%3};"
        : "+f"(d[0]), "+f"(d[1]), "+f"(d[2]), "+f"(d[3])
        : "r"(a0), "r"(a1), "r"(a2), "r"(a3), "r"(b0), "r"(b1));
}

// ---------------- SMEM layout (bytes) ----------------------------------------
#define OFF_RECV   0        /* 512 */
#define OFF_SEND   512      /* 512 */
#define OFF_BE     1024     /* 512 */
#define OFF_B2V    1536     /* 512 */
#define OFF_WCH    2048     /* 2 x 8192  frag-W chunk buffers */
#define OFF_ACH    18432    /* 2 x 10240 A chunk buffers [128][20] */
#define OFF_A2     38912    /* 128 x 132 floats = 67584 */
#define SMEM_TOTAL 106496

// ---------------- MMA over one K=16 chunk ------------------------------------
// As: uint32 view of A rows (stride AST floats), 16 cols of this chunk
// Wc: fragment-ordered weights (float4[nb*32+lane]), nb = global n>>3
__device__ __forceinline__ void mma_frag_chunk(float (&acc)[2][8][4],
        const uint32_t* As, int AST, const float4* Wc, int wm, int wn, int lid)
{
    const int g = lid >> 2, tg = lid & 3;
    uint32_t a[2][2][4];
#pragma unroll
    for (int f = 0; f < 2; f++) {
        const uint32_t* p = As + (wm * 32 + f * 16 + g) * AST + tg;
#pragma unroll
        for (int ks = 0; ks < 2; ks++) {
            a[f][ks][0] = p[ks * 8];
            a[f][ks][1] = p[8 * AST + ks * 8];
            a[f][ks][2] = p[ks * 8 + 4];
            a[f][ks][3] = p[8 * AST + ks * 8 + 4];
        }
    }
    const float4* wp = Wc + wn * 256 + lid;
#pragma unroll
    for (int nt = 0; nt < 8; nt++) {
        float4 bv = wp[nt * 32];
        uint32_t bx = __float_as_uint(bv.x), by = __float_as_uint(bv.y);
        uint32_t bz = __float_as_uint(bv.z), bw = __float_as_uint(bv.w);
        mma8(acc[0][nt], a[0][0][0], a[0][0][1], a[0][0][2], a[0][0][3], bx, by);
        mma8(acc[1][nt], a[1][0][0], a[1][0][1], a[1][0][2], a[1][0][3], bx, by);
        mma8(acc[0][nt], a[0][1][0], a[0][1][1], a[0][1][2], a[0][1][3], bz, bw);
        mma8(acc[1][nt], a[1][1][0], a[1][1][1], a[1][1][2], a[1][1][3], bz, bw);
    }
}

__device__ __forceinline__ void issue_aw(int c, int buf, uint32_t sb, int tid,
        const float* Asrc, int row0, const float* Wfrag)
{
#pragma unroll
    for (int i = 0; i < 2; i++) {
        int idx4 = i * 256 + tid;
        int row = idx4 >> 2, c4 = idx4 & 3;
        cp16(sb + OFF_ACH + buf * 10240 + row * 80 + c4 * 16,
             Asrc + (size_t)(row0 + row) * 128 + c * 16 + c4 * 4);
    }
#pragma unroll
    for (int i = 0; i < 2; i++) {
        int idx = i * 256 + tid;
        cp16(sb + OFF_WCH + buf * 8192 + idx * 16, Wfrag + c * 2048 + idx * 4);
    }
    asm volatile("cp.async.commit_group;");
}
__device__ __forceinline__ void issue_w(int c, int buf, uint32_t sb, int tid,
                                        const float* Wfrag)
{
#pragma unroll
    for (int i = 0; i < 2; i++) {
        int idx = i * 256 + tid;
        cp16(sb + OFF_WCH + buf * 8192 + idx * 16, Wfrag + c * 2048 + idx * 4);
    }
    asm volatile("cp.async.commit_group;");
}

// layer over K=128: A rows streamed from gmem, W fragment-streamed
__device__ __forceinline__ void layer_k128(float (&acc)[2][8][4], char* smem, uint32_t sb,
        const float* Asrc, int row0, const float* Wfrag,
        int wm, int wn, int lid, int tid, bool preissued)
{
    if (!preissued) {
        issue_aw(0, 0, sb, tid, Asrc, row0, Wfrag);
        issue_aw(1, 1, sb, tid, Asrc, row0, Wfrag);
    }
    for (int c = 0; c < 8; c++) {
        int buf = c & 1;
        if (c < 7) asm volatile("cp.async.wait_group 1;");
        else       asm volatile("cp.async.wait_group 0;");
        __syncthreads();
        mma_frag_chunk(acc, (const uint32_t*)(smem + OFF_ACH + buf * 10240), 20,
                       (const float4*)(smem + OFF_WCH + buf * 8192), wm, wn, lid);
        __syncthreads();
        if (c + 2 < 8) issue_aw(c + 2, buf, sb, tid, Asrc, row0, Wfrag);
    }
}
// layer2 over K=128: A resident in A2[128][132], W fragment-streamed
__device__ __forceinline__ void layer2_k128(float (&acc)[2][8][4], char* smem, uint32_t sb,
        const float* Wfrag, int wm, int wn, int lid, int tid)
{
    issue_w(0, 0, sb, tid, Wfrag);
    issue_w(1, 1, sb, tid, Wfrag);
    for (int c = 0; c < 8; c++) {
        int buf = c & 1;
        if (c < 7) asm volatile("cp.async.wait_group 1;");
        else       asm volatile("cp.async.wait_group 0;");
        __syncthreads();
        mma_frag_chunk(acc, (const uint32_t*)(smem + OFF_A2) + c * 16, 132,
                       (const float4*)(smem + OFF_WCH + buf * 8192), wm, wn, lid);
        __syncthreads();
        if (c + 2 < 8) issue_w(c + 2, buf, sb, tid, Wfrag);
    }
}

// epi1: acc + bias (+G preloaded in A2) -> ELU -> round -> A2; reset acc
template<bool ADDG>
__device__ __forceinline__ void epi1(float (&acc)[2][8][4], char* smem,
                                     int wm, int wn, int lid)
{
    float* A2 = (float*)(smem + OFF_A2);
    const float* be = (const float*)(smem + OFF_BE);
    const int g = lid >> 2, tg = lid & 3;
#pragma unroll
    for (int f = 0; f < 2; f++) {
        int r = wm * 32 + f * 16 + g;
#pragma unroll
        for (int nt = 0; nt < 8; nt++) {
            int n0 = wn * 64 + nt * 8 + tg * 2;
            float be0 = be[n0], be1 = be[n0 + 1];
            float g0x = 0.f, g0y = 0.f, g1x = 0.f, g1y = 0.f;
            if (ADDG) {
                float2 G0 = *(float2*)(A2 + r * 132 + n0);
                float2 G1 = *(float2*)(A2 + (r + 8) * 132 + n0);
                g0x = G0.x; g0y = G0.y; g1x = G1.x; g1y = G1.y;
            }
            float v0 = acc[f][nt][0] + be0 + g0x;
            float v1 = acc[f][nt][1] + be1 + g0y;
            float v2 = acc[f][nt][2] + be0 + g1x;
            float v3 = acc[f][nt][3] + be1 + g1y;
            v0 = (v0 > 0.f) ? v0 : expm1f(v0);
            v1 = (v1 > 0.f) ? v1 : expm1f(v1);
            v2 = (v2 > 0.f) ? v2 : expm1f(v2);
            v3 = (v3 > 0.f) ? v3 : expm1f(v3);
            *(float2*)(A2 + r * 132 + n0)       = make_float2(rtf(v0), rtf(v1));
            *(float2*)(A2 + (r + 8) * 132 + n0) = make_float2(rtf(v2), rtf(v3));
#pragma unroll
            for (int q = 0; q < 4; q++) acc[f][nt][q] = 0.f;
        }
    }
}
// epi2: acc + b2 -> ELU -> (round?) -> A2
template<bool ROUND>
__device__ __forceinline__ void epi2(float (&acc)[2][8][4], char* smem,
                                     int wm, int wn, int lid)
{
    float* A2 = (float*)(smem + OFF_A2);
    const float* be = (const float*)(smem + OFF_B2V);
    const int g = lid >> 2, tg = lid & 3;
#pragma unroll
    for (int f = 0; f < 2; f++) {
        int r = wm * 32 + f * 16 + g;
#pragma unroll
        for (int nt = 0; nt < 8; nt++) {
            int n0 = wn * 64 + nt * 8 + tg * 2;
            float be0 = be[n0], be1 = be[n0 + 1];
            float v0 = acc[f][nt][0] + be0;
            float v1 = acc[f][nt][1] + be1;
            float v2 = acc[f][nt][2] + be0;
            float v3 = acc[f][nt][3] + be1;
            v0 = (v0 > 0.f) ? v0 : expm1f(v0);
            v1 = (v1 > 0.f) ? v1 : expm1f(v1);
            v2 = (v2 > 0.f) ? v2 : expm1f(v2);
            v3 = (v3 > 0.f) ? v3 : expm1f(v3);
            if (ROUND) { v0 = rtf(v0); v1 = rtf(v1); v2 = rtf(v2); v3 = rtf(v3); }
            *(float2*)(A2 + r * 132 + n0)       = make_float2(v0, v1);
            *(float2*)(A2 + (r + 8) * 132 + n0) = make_float2(v2, v3);
        }
    }
}
__device__ __forceinline__ void flush_out(char* smem, float* out, int row0, int tid,
        int ostride, int ocol, bool stats, float* psum, float* psq, int bx)
{
    const float* A2 = (const float*)(smem + OFF_A2);
#pragma unroll
    for (int i = 0; i < 16; i++) {
        int idx4 = i * 256 + tid;
        int row = idx4 >> 5, c4 = idx4 & 31;
        float4 v = *(const float4*)(A2 + row * 132 + c4 * 4);
        *(float4*)(out + (size_t)(row0 + row) * ostride + ocol + c4 * 4) = v;
    }
    if (stats && tid < 128) {
        float S = 0.f, Q = 0.f;
#pragma unroll 8
        for (int r = 0; r < 128; r++) {
            float x = A2[r * 132 + tid];
            S += x;
            Q += x * x;
        }
        psum[(size_t)bx * 128 + tid] = S;
        psq [(size_t)bx * 128 + tid] = Q;
    }
}
__device__ __forceinline__ void fill_edges(char* smem, int row0, int tid) {
    if (tid < 128) {
        int row = row0 + tid;
        int b = row / NEDGE;
        int e = row - b * NEDGE;
        int r = e / 23;
        int j = e - r * 23;
        int s = j + (j >= r);
        ((int*)(smem + OFF_RECV))[tid] = b * NKPS + r;
        ((int*)(smem + OFF_SEND))[tid] = b * NKPS + s;
    }
}
#define ACC_DECL float acc[2][8][4]; \
    _Pragma("unroll") for (int f_ = 0; f_ < 2; f_++) \
    _Pragma("unroll") for (int n_ = 0; n_ < 8; n_++) \
    _Pragma("unroll") for (int q_ = 0; q_ < 4; q_++) acc[f_][n_][q_] = 0.f;

// =================== kernels ==================================================
__global__ __launch_bounds__(256, 2)
void stage1_mlp(const float* __restrict__ X, const float* __restrict__ W1,
                const float* __restrict__ b1, const float* __restrict__ W2frag,
                const float* __restrict__ b2, float* __restrict__ out,
                float* __restrict__ psum, float* __restrict__ psq)
{
    extern __shared__ char smem[];
    const uint32_t sb = smem_u32(smem);
    const int tid = threadIdx.x, wid = tid >> 5, lid = tid & 31;
    const int wm = wid & 3, wn = wid >> 2;
    const int row0 = blockIdx.x * 128;
    float* smf = (float*)smem;
    if (tid < 128) { smf[OFF_BE/4 + tid] = b1[tid]; smf[OFF_B2V/4 + tid] = b2[tid]; }
#pragma unroll
    for (int i = 0; i < 8; i++) {                       // A [128][20], pad 6->16
        int idx = i * 256 + tid;
        int row = idx >> 4, col = idx & 15;
        float av = (col < 6) ? X[(size_t)(row0 + row) * 6 + col] : 0.f;
        smf[OFF_ACH/4 + row * 20 + col] = rtf(av);
    }
#pragma unroll
    for (int i = 0; i < 8; i++) {                       // W1 frags inline (2048)
        int o = i * 256 + tid;
        int f4 = o >> 2, reg = o & 3;
        int nb = f4 >> 5, lane = f4 & 31, gg = lane >> 2, tg = lane & 3;
        int n = nb * 8 + gg;
        int k = (reg >> 1) * 8 + (reg & 1) * 4 + tg;
        smf[OFF_WCH/4 + o] = rtf((k < 6) ? W1[n * 6 + k] : 0.f);
    }
    __syncthreads();
    ACC_DECL
    mma_frag_chunk(acc, (const uint32_t*)(smem + OFF_ACH), 20,
                   (const float4*)(smem + OFF_WCH), wm, wn, lid);
    epi1<false>(acc, smem, wm, wn, lid);
    __syncthreads();
    layer2_k128(acc, smem, sb, W2frag, wm, wn, lid, tid);
    epi2<true>(acc, smem, wm, wn, lid);
    __syncthreads();
    flush_out(smem, out, row0, tid, 128, 0, true, psum, psq, blockIdx.x);
}

__global__ __launch_bounds__(256, 2)
void node_mlp(const float* __restrict__ A, const float* __restrict__ W1frag,
              const float* __restrict__ b1, const float* __restrict__ W2frag,
              const float* __restrict__ b2, float* __restrict__ out,
              float* __restrict__ psum, float* __restrict__ psq)
{
    extern __shared__ char smem[];
    const uint32_t sb = smem_u32(smem);
    const int tid = threadIdx.x, wid = tid >> 5, lid = tid & 31;
    const int wm = wid & 3, wn = wid >> 2;
    const int row0 = blockIdx.x * 128;
    float* smf = (float*)smem;
    if (tid < 128) { smf[OFF_BE/4 + tid] = b1[tid]; smf[OFF_B2V/4 + tid] = b2[tid]; }
    __syncthreads();
    ACC_DECL
    layer_k128(acc, smem, sb, A, row0, W1frag, wm, wn, lid, tid, false);
    epi1<false>(acc, smem, wm, wn, lid);
    __syncthreads();
    layer2_k128(acc, smem, sb, W2frag, wm, wn, lid, tid);
    epi2<true>(acc, smem, wm, wn, lid);
    __syncthreads();
    flush_out(smem, out, row0, tid, 128, 0, true, psum, psq, blockIdx.x);
}

// PS[:, blk*128 : +128] = A @ Wfrag(blk)^T, raw fp32
__global__ __launch_bounds__(256, 2)
void gemm_node(const float* __restrict__ A, const float* __restrict__ Wfrag,
               float* __restrict__ PS)
{
    extern __shared__ char smem[];
    const uint32_t sb = smem_u32(smem);
    const int tid = threadIdx.x, wid = tid >> 5, lid = tid & 31;
    const int wm = wid & 3, wn = wid >> 2;
    const int row0 = blockIdx.x * 128;
    const int blk = blockIdx.y;
    ACC_DECL
    layer_k128(acc, smem, sb, A, row0, Wfrag + (size_t)blk * 16384, wm, wn, lid, tid, false);
    float* A2 = (float*)(smem + OFF_A2);
    const int g = lid >> 2, tg = lid & 3;
#pragma unroll
    for (int f = 0; f < 2; f++) {
        int r = wm * 32 + f * 16 + g;
#pragma unroll
        for (int nt = 0; nt < 8; nt++) {
            int n0 = wn * 64 + nt * 8 + tg * 2;
            *(float2*)(A2 + r * 132 + n0)       = make_float2(acc[f][nt][0], acc[f][nt][1]);
            *(float2*)(A2 + (r + 8) * 132 + n0) = make_float2(acc[f][nt][2], acc[f][nt][3]);
        }
    }
    __syncthreads();
    flush_out(smem, PS, row0, tid, 256, blk * 128, false, nullptr, nullptr, 0);
}

// stage 2 edges: A2 = round(ELU(P[recv]+S[send]+beff)); layer2; h2 + stats
__global__ __launch_bounds__(256, 2)
void edge_stage2(const float* __restrict__ PS, const float* __restrict__ beff,
                 const float* __restrict__ W2frag, const float* __restrict__ b2,
                 float* __restrict__ out, float* __restrict__ psum, float* __restrict__ psq)
{
    extern __shared__ char smem[];
    const uint32_t sb = smem_u32(smem);
    const int tid = threadIdx.x, wid = tid >> 5, lid = tid & 31;
    const int wm = wid & 3, wn = wid >> 2;
    const int row0 = blockIdx.x * 128;
    float* smf = (float*)smem;
    fill_edges(smem, row0, tid);
    if (tid < 128) { smf[OFF_BE/4 + tid] = beff[tid]; smf[OFF_B2V/4 + tid] = b2[tid]; }
    __syncthreads();
    const int* rs = (const int*)(smem + OFF_RECV);
    const int* ss = (const int*)(smem + OFF_SEND);
    float* A2 = (float*)(smem + OFF_A2);
    const float* be = smf + OFF_BE/4;
#pragma unroll
    for (int i = 0; i < 16; i++) {
        int idx4 = i * 256 + tid;
        int row = idx4 >> 5, c4 = idx4 & 31;
        float4 p = *(const float4*)(PS + (size_t)rs[row] * 256 + c4 * 4);
        float4 s = *(const float4*)(PS + (size_t)ss[row] * 256 + 128 + c4 * 4);
        float v0 = p.x + s.x + be[c4 * 4];
        float v1 = p.y + s.y + be[c4 * 4 + 1];
        float v2 = p.z + s.z + be[c4 * 4 + 2];
        float v3 = p.w + s.w + be[c4 * 4 + 3];
        v0 = (v0 > 0.f) ? v0 : expm1f(v0);
        v1 = (v1 > 0.f) ? v1 : expm1f(v1);
        v2 = (v2 > 0.f) ? v2 : expm1f(v2);
        v3 = (v3 > 0.f) ? v3 : expm1f(v3);
        *(float4*)(A2 + row * 132 + c4 * 4) = make_float4(rtf(v0), rtf(v1), rtf(v2), rtf(v3));
    }
    ACC_DECL
    layer2_k128(acc, smem, sb, W2frag, wm, wn, lid, tid);
    epi2<true>(acc, smem, wm, wn, lid);
    __syncthreads();
    flush_out(smem, out, row0, tid, 128, 0, true, psum, psq, blockIdx.x);
}

// stage 4 edges: G = P3[recv]+S3[send] -> A2; skip MMA over H2; epi1 adds G; layer2 -> h4
__global__ __launch_bounds__(256, 2)
void edge_stage4(const float* __restrict__ PS3, const float* __restrict__ H2,
                 const float* __restrict__ SKIPfrag, const float* __restrict__ beff,
                 const float* __restrict__ W2frag, const float* __restrict__ b2,
                 float* __restrict__ out, float* __restrict__ psum, float* __restrict__ psq)
{
    extern __shared__ char smem[];
    const uint32_t sb = smem_u32(smem);
    const int tid = threadIdx.x, wid = tid >> 5, lid = tid & 31;
    const int wm = wid & 3, wn = wid >> 2;
    const int row0 = blockIdx.x * 128;
    float* smf = (float*)smem;
    fill_edges(smem, row0, tid);
    if (tid < 128) { smf[OFF_BE/4 + tid] = beff[tid]; smf[OFF_B2V/4 + tid] = b2[tid]; }
    issue_aw(0, 0, sb, tid, H2, row0, SKIPfrag);
    issue_aw(1, 1, sb, tid, H2, row0, SKIPfrag);
    __syncthreads();
    const int* rs = (const int*)(smem + OFF_RECV);
    const int* ss = (const int*)(smem + OFF_SEND);
    float* A2 = (float*)(smem + OFF_A2);
#pragma unroll
    for (int i = 0; i < 16; i++) {
        int idx4 = i * 256 + tid;
        int row = idx4 >> 5, c4 = idx4 & 31;
        float4 p = *(const float4*)(PS3 + (size_t)rs[row] * 256 + c4 * 4);
        float4 s = *(const float4*)(PS3 + (size_t)ss[row] * 256 + 128 + c4 * 4);
        *(float4*)(A2 + row * 132 + c4 * 4) =
            make_float4(p.x + s.x, p.y + s.y, p.z + s.z, p.w + s.w);
    }
    ACC_DECL
    layer_k128(acc, smem, sb, H2, row0, SKIPfrag, wm, wn, lid, tid, true);
    epi1<true>(acc, smem, wm, wn, lid);
    __syncthreads();
    layer2_k128(acc, smem, sb, W2frag, wm, wn, lid, tid);
    epi2<false>(acc, smem, wm, wn, lid);
    __syncthreads();
    flush_out(smem, out, row0, tid, 128, 0, true, psum, psq, blockIdx.x);
}

// ---- prep: fragment-order one 128-col block of W, optional per-k scale -------
__global__ void prep_frag(const float* __restrict__ W, int Kin, int kofs,
                          const float* __restrict__ sv, float* __restrict__ dst)
{
    int o = blockIdx.x * 256 + threadIdx.x;   // 16384
    int c = o >> 11, rem = o & 2047;
    int f4 = rem >> 2, reg = rem & 3;
    int nb = f4 >> 5, lane = f4 & 31;
    int g = lane >> 2, tg = lane & 3;
    int n = nb * 8 + g;
    int k = c * 16 + (reg >> 1) * 8 + (reg & 1) * 4 + tg;
    float v = W[(size_t)n * Kin + kofs + k];
    if (sv) v *= sv[k];
    dst[o] = __uint_as_float(f2tf(v));
}
// beff[n] = b[n] + sum_k W[n][k]*t(k); t = ta[k&127] (k<256), tb[k-256] (k>=256)
__global__ void bias_fold(const float* __restrict__ W, int Kin, const float* __restrict__ b,
                          const float* __restrict__ ta, const float* __restrict__ tb,
                          float* __restrict__ beff)
{
    const int n = blockIdx.x, tid = threadIdx.x;   // 128 thr
    float partial = 0.f;
    for (int k = tid; k < Kin; k += 128) {
        float t = (k < 256) ? ta[k & 127] : tb[k - 256];
        partial += W[(size_t)n * Kin + k] * t;
    }
    __shared__ float red[128];
    red[tid] = partial;
    __syncthreads();
    for (int off = 64; off; off >>= 1) {
        if (tid < off) red[tid] += red[tid + off];
        __syncthreads();
    }
    if (tid == 0) beff[n] = b[n] + red[0];
}

__global__ void bn_finalize(const float* __restrict__ psum, const float* __restrict__ psq,
                            int nblocks, float Minv,
                            const float* __restrict__ g, const float* __restrict__ be,
                            float* __restrict__ s, float* __restrict__ t)
{
    const int tid = threadIdx.x;
    const int c = tid & 127, part = tid >> 7;
    float S = 0.f, Q = 0.f;
    for (int i = part; i < nblocks; i += 8) {
        S += psum[(size_t)i * 128 + c];
        Q += psq [(size_t)i * 128 + c];
    }
    __shared__ float sS[8][128], sQ[8][128];
    sS[part][c] = S;
    sQ[part][c] = Q;
    __syncthreads();
    if (tid < 128) {
        float St = 0.f, Qt = 0.f;
#pragma unroll
        for (int p = 0; p < 8; p++) { St += sS[p][tid]; Qt += sQ[p][tid]; }
        float mean = St * Minv;
        float var  = Qt * Minv - mean * mean;
        float inv  = rsqrtf(var + BN_EPS);
        float sv   = g[tid] * inv;
        s[tid] = sv;
        t[tid] = be[tid] - mean * sv;
    }
}

template<bool R>
__global__ void edge2node(const float* __restrict__ h,
                          const float* __restrict__ s, const float* __restrict__ t,
                          float* __restrict__ outn)
{
    int c  = threadIdx.x;
    int bn = blockIdx.x;
    const float* p = h + (size_t)bn * 23 * 128 + c;
    float acc = 0.f;
#pragma unroll
    for (int j = 0; j < 23; j++) acc += p[(size_t)j * 128];
    float val = (s[c] * acc + 23.f * t[c]) * (1.f / 24.f);
    if (R) val = rtf(val);
    outn[(size_t)bn * 128 + c] = val;
}

__global__ void final_proj(const float* __restrict__ node4,
                           const float* __restrict__ fo_w, const float* __restrict__ fo_b,
                           float* __restrict__ out)
{
    int b = blockIdx.x;
    int c = threadIdx.x;
    float a0 = 0.f, a1 = 0.f;
#pragma unroll
    for (int n = 0; n < NKPS; n++) {
        float v = node4[((size_t)b * NKPS + n) * 128 + c];
        a0 = fmaf(v, fo_w[n * 128 + c],        a0);
        a1 = fmaf(v, fo_w[3072 + n * 128 + c], a1);
    }
    __shared__ float r0[128], r1[128];
    r0[c] = a0; r1[c] = a1;
    __syncthreads();
    for (int off = 64; off; off >>= 1) {
        if (c < off) { r0[c] += r0[c + off]; r1[c] += r1[c + off]; }
        __syncthreads();
    }
    if (c == 0) {
        out[b * 2 + 0] = r0[0] + fo_b[0];
        out[b * 2 + 1] = r1[0] + fo_b[1];
    }
}

// ---- launch -------------------------------------------------------------------
extern "C" void kernel_launch(void* const* d_in, const int* in_sizes, int n_in,
                              void* d_out, int out_size)
{
    const float** I = (const float**)d_in;
    const float* inputs = I[0];
    const float *fo_w = I[3], *fo_b = I[4];
    const float *m1w1 = I[5],  *m1b1 = I[6],  *m1w2 = I[7],  *m1b2 = I[8],  *m1g = I[9],  *m1be = I[10];
    const float *m2w1 = I[11], *m2b1 = I[12], *m2w2 = I[13], *m2b2 = I[14], *m2g = I[15], *m2be = I[16];
    const float *m3w1 = I[17], *m3b1 = I[18], *m3w2 = I[19], *m3b2 = I[20], *m3g = I[21], *m3be = I[22];
    const float *m4w1 = I[23], *m4b1 = I[24], *m4w2 = I[25], *m4b2 = I[26], *m4g = I[27], *m4be = I[28];
    float* out = (float*)d_out;

    float *bufA, *bufB, *n1, *n2, *n3, *ps, *psfrag, *skipfrag, *w1frag, *l2frag;
    float *beff, *psum, *psq, *sA, *tA;
    cudaGetSymbolAddress((void**)&bufA, g_bufA);
    cudaGetSymbolAddress((void**)&bufB, g_bufB);
    cudaGetSymbolAddress((void**)&n1, g_n1);
    cudaGetSymbolAddress((void**)&n2, g_n2);
    cudaGetSymbolAddress((void**)&n3, g_n3);
    cudaGetSymbolAddress((void**)&ps, g_ps);
    cudaGetSymbolAddress((void**)&psfrag, g_psfrag);
    cudaGetSymbolAddress((void**)&skipfrag, g_skipfrag);
    cudaGetSymbolAddress((void**)&w1frag, g_w1frag);
    cudaGetSymbolAddress((void**)&l2frag, g_l2frag);
    cudaGetSymbolAddress((void**)&beff, g_beff);
    cudaGetSymbolAddress((void**)&psum, g_psum);
    cudaGetSymbolAddress((void**)&psq, g_psq);
    cudaGetSymbolAddress((void**)&sA, g_s);
    cudaGetSymbolAddress((void**)&tA, g_t);

    cudaFuncSetAttribute(stage1_mlp,  cudaFuncAttributeMaxDynamicSharedMemorySize, SMEM_TOTAL);
    cudaFuncSetAttribute(node_mlp,    cudaFuncAttributeMaxDynamicSharedMemorySize, SMEM_TOTAL);
    cudaFuncSetAttribute(gemm_node,   cudaFuncAttributeMaxDynamicSharedMemorySize, SMEM_TOTAL);
    cudaFuncSetAttribute(edge_stage2, cudaFuncAttributeMaxDynamicSharedMemorySize, SMEM_TOTAL);
    cudaFuncSetAttribute(edge_stage4, cudaFuncAttributeMaxDynamicSharedMemorySize, SMEM_TOTAL);

    const int GN = M_NODE / 128;   // 192
    const int GE = M_EDGE / 128;   // 4416
    const float MinvN = 1.0f / (float)M_NODE;
    const float MinvE = 1.0f / (float)M_EDGE;
    dim3 gnode(GN, 2);

    // ---- stage 1 ----
    prep_frag<<<64, 256>>>(m1w2, 128, 0, nullptr, l2frag);
    stage1_mlp<<<GN, 256, SMEM_TOTAL>>>(inputs, m1w1, m1b1, l2frag, m1b2, n1, psum, psq);
    bn_finalize<<<1, 1024>>>(psum, psq, GN, MinvN, m1g, m1be, sA + 0, tA + 0);

    // ---- stage 2 ----
    prep_frag<<<64, 256>>>(m2w1, 256, 0,   sA + 0, psfrag);
    prep_frag<<<64, 256>>>(m2w1, 256, 128, sA + 0, psfrag + 16384);
    prep_frag<<<64, 256>>>(m2w2, 128, 0, nullptr, l2frag);
    bias_fold<<<128, 128>>>(m2w1, 256, m2b1, tA + 0, nullptr, beff);
    gemm_node<<<gnode, 256, SMEM_TOTAL>>>(n1, psfrag, ps);
    edge_stage2<<<GE, 256, SMEM_TOTAL>>>(ps, beff, l2frag, m2b2, bufA, psum, psq);
    bn_finalize<<<1, 1024>>>(psum, psq, GE, MinvE, m2g, m2be, sA + 128, tA + 128);
    edge2node<true><<<M_NODE, 128>>>(bufA, sA + 128, tA + 128, n2);

    // ---- stage 3 ----
    prep_frag<<<64, 256>>>(m3w1, 128, 0, nullptr, w1frag);
    prep_frag<<<64, 256>>>(m3w2, 128, 0, nullptr, l2frag);
    node_mlp<<<GN, 256, SMEM_TOTAL>>>(n2, w1frag, m3b1, l2frag, m3b2, n3, psum, psq);
    bn_finalize<<<1, 1024>>>(psum, psq, GN, MinvN, m3g, m3be, sA + 256, tA + 256);

    // ---- stage 4 ----
    prep_frag<<<64, 256>>>(m4w1, 384, 0,   sA + 256, psfrag);
    prep_frag<<<64, 256>>>(m4w1, 384, 128, sA + 256, psfrag + 16384);
    prep_frag<<<64, 256>>>(m4w1, 384, 256, sA + 128, skipfrag);
    prep_frag<<<64, 256>>>(m4w2, 128, 0, nullptr, l2frag);
    bias_fold<<<128, 128>>>(m4w1, 384, m4b1, tA + 256, tA + 128, beff);
    gemm_node<<<gnode, 256, SMEM_TOTAL>>>(n3, psfrag, ps);
    edge_stage4<<<GE, 256, SMEM_TOTAL>>>(ps, bufA, skipfrag, beff, l2frag, m4b2, bufB, psum, psq);
    bn_finalize<<<1, 1024>>>(psum, psq, GE, MinvE, m4g, m4be, sA + 384, tA + 384);

    edge2node<false><<<M_NODE, 128>>>(bufB, sA + 384, tA + 384, n2);
    final_proj<<<BATCH, 128>>>(n2, fo_w, fo_b, out);
}

// round 7
// speedup vs baseline: 1.2871x; 1.0229x over previous
#include <cuda_runtime.h>
#include <math.h>
#include <stdint.h>

#define BATCH   1024
#define NKPS    24
#define NEDGE   552
#define M_NODE  (BATCH*NKPS)    // 24576
#define M_EDGE  (BATCH*NEDGE)   // 565248
#define GE_BLK  (M_EDGE/128)    // 4416
#define BN_EPS  1e-5f

// ---------------- scratch (device globals) ---------------------------------
__device__ float g_bufA[(size_t)M_EDGE*128];   // h2 (x_skip), tf32-rounded
__device__ float g_n1 [(size_t)M_NODE*128];    // h1 rounded
__device__ float g_n2 [(size_t)M_NODE*128];    // node2 (rounded) / node4 (fp32)
__device__ float g_n3 [(size_t)M_NODE*128];    // h3 rounded
__device__ float g_ps [(size_t)M_NODE*256];    // P|S per node, fp32
__device__ float g_pnode[(size_t)GE_BLK*7*128];// per-block node partial sums
__device__ float g_psfrag[2*16384];
__device__ float g_skipfrag[16384];
__device__ float g_w1frag[16384];
__device__ float g_l2frag[16384];
__device__ float g_beff[128];
__device__ float g_psum[GE_BLK*128];
__device__ float g_psq [GE_BLK*128];
__device__ float g_s[4*128];
__device__ float g_t[4*128];

// ---------------- helpers ----------------------------------------------------
__device__ __forceinline__ uint32_t smem_u32(const void* p) {
    uint32_t a;
    asm("{ .reg .u64 t; cvta.to.shared.u64 t, %1; cvt.u32.u64 %0, t; }" : "=r"(a) : "l"(p));
    return a;
}
__device__ __forceinline__ void cp16(uint32_t dst, const void* src) {
    asm volatile("cp.async.cg.shared.global [%0], [%1], 16;" :: "r"(dst), "l"(src));
}
__device__ __forceinline__ uint32_t f2tf(float x) {
    uint32_t u;
    asm("cvt.rna.tf32.f32 %0, %1;" : "=r"(u) : "f"(x));
    return u;
}
__device__ __forceinline__ float rtf(float x) { return __uint_as_float(f2tf(x)); }
__device__ __forceinline__ void mma8(float d[4],
                                     uint32_t a0, uint32_t a1, uint32_t a2, uint32_t a3,
                                     uint32_t b0, uint32_t b1) {
    asm volatile("mma.sync.aligned.m16n8k8.row.col.f32.tf32.tf32.f32 "
        "{%0,%1,%2,%3}, {%4,%5,%6,%7}, {%8,%9}, {%0,%1,%2,%3};"
        : "+f"(d[0]), "+f"(d[1]), "+f"(d[2]), "+f"(d[3])
        : "r"(a0), "r"(a1), "r"(a2), "r"(a3), "r"(b0), "r"(b1));
}

// ---------------- SMEM layout (bytes) ----------------------------------------
// Region R (OFF_ACH..OFF_A2): layer-1 A chunks [2x10240] + W16 chunks [2x8192];
// layer-2 overlays W32 chunks [2x16384] at OFF_ACH (safe: layer-1 drained).
#define OFF_RECV   0
#define OFF_SEND   512
#define OFF_BE     1024
#define OFF_B2V    1536
#define OFF_ACH    2048     /* layer-1 A chunks; layer-2 W32 chunks */
#define OFF_WCH    22528    /* layer-1 W16 chunks */
#define OFF_A2     38912    /* 128 x 132 floats = 67584 */
#define SMEM_TOTAL 106496

// ---------------- MMA over one K=16 chunk ------------------------------------
__device__ __forceinline__ void mma_frag_chunk(float (&acc)[2][8][4],
        const uint32_t* As, int AST, const float4* Wc, int wm, int wn, int lid)
{
    const int g = lid >> 2, tg = lid & 3;
    uint32_t a[2][2][4];
#pragma unroll
    for (int f = 0; f < 2; f++) {
        const uint32_t* p = As + (wm * 32 + f * 16 + g) * AST + tg;
#pragma unroll
        for (int ks = 0; ks < 2; ks++) {
            a[f][ks][0] = p[ks * 8];
            a[f][ks][1] = p[8 * AST + ks * 8];
            a[f][ks][2] = p[ks * 8 + 4];
            a[f][ks][3] = p[8 * AST + ks * 8 + 4];
        }
    }
    const float4* wp = Wc + wn * 256 + lid;
#pragma unroll
    for (int nt = 0; nt < 8; nt++) {
        float4 bv = wp[nt * 32];
        uint32_t bx = __float_as_uint(bv.x), by = __float_as_uint(bv.y);
        uint32_t bz = __float_as_uint(bv.z), bw = __float_as_uint(bv.w);
        mma8(acc[0][nt], a[0][0][0], a[0][0][1], a[0][0][2], a[0][0][3], bx, by);
        mma8(acc[1][nt], a[1][0][0], a[1][0][1], a[1][0][2], a[1][0][3], bx, by);
        mma8(acc[0][nt], a[0][1][0], a[0][1][1], a[0][1][2], a[0][1][3], bz, bw);
        mma8(acc[1][nt], a[1][1][0], a[1][1][1], a[1][1][2], a[1][1][3], bz, bw);
    }
}

__device__ __forceinline__ void issue_aw(int c, int buf, uint32_t sb, int tid,
        const float* Asrc, int row0, const float* Wfrag)
{
#pragma unroll
    for (int i = 0; i < 2; i++) {
        int idx4 = i * 256 + tid;
        int row = idx4 >> 2, c4 = idx4 & 3;
        cp16(sb + OFF_ACH + buf * 10240 + row * 80 + c4 * 16,
             Asrc + (size_t)(row0 + row) * 128 + c * 16 + c4 * 4);
    }
#pragma unroll
    for (int i = 0; i < 2; i++) {
        int idx = i * 256 + tid;
        cp16(sb + OFF_WCH + buf * 8192 + idx * 16, Wfrag + c * 2048 + idx * 4);
    }
    asm volatile("cp.async.commit_group;");
}
__device__ __forceinline__ void issue_w32(int c, int buf, uint32_t sb, int tid,
                                          const float* Wfrag)
{
#pragma unroll
    for (int i = 0; i < 4; i++) {
        int idx = i * 256 + tid;
        cp16(sb + OFF_ACH + buf * 16384 + idx * 16, Wfrag + c * 4096 + idx * 4);
    }
    asm volatile("cp.async.commit_group;");
}

// layer-1 over K=128: A rows streamed from gmem, W16 fragment-streamed
__device__ __forceinline__ void layer_k128(float (&acc)[2][8][4], char* smem, uint32_t sb,
        const float* Asrc, int row0, const float* Wfrag,
        int wm, int wn, int lid, int tid, bool preissued)
{
    if (!preissued) {
        issue_aw(0, 0, sb, tid, Asrc, row0, Wfrag);
        issue_aw(1, 1, sb, tid, Asrc, row0, Wfrag);
    }
    for (int c = 0; c < 8; c++) {
        int buf = c & 1;
        if (c < 7) asm volatile("cp.async.wait_group 1;");
        else       asm volatile("cp.async.wait_group 0;");
        __syncthreads();
        mma_frag_chunk(acc, (const uint32_t*)(smem + OFF_ACH + buf * 10240), 20,
                       (const float4*)(smem + OFF_WCH + buf * 8192), wm, wn, lid);
        __syncthreads();
        if (c + 2 < 8) issue_aw(c + 2, buf, sb, tid, Asrc, row0, Wfrag);
    }
}
// layer-2 over K=128: A resident in A2[128][132], W32 fragment-streamed
__device__ __forceinline__ void layer2_k128(float (&acc)[2][8][4], char* smem, uint32_t sb,
        const float* Wfrag, int wm, int wn, int lid, int tid)
{
    issue_w32(0, 0, sb, tid, Wfrag);
    issue_w32(1, 1, sb, tid, Wfrag);
    for (int c = 0; c < 4; c++) {
        int buf = c & 1;
        if (c < 3) asm volatile("cp.async.wait_group 1;");
        else       asm volatile("cp.async.wait_group 0;");
        __syncthreads();
        mma_frag_chunk(acc, (const uint32_t*)(smem + OFF_A2) + c * 32, 132,
                       (const float4*)(smem + OFF_ACH + buf * 16384), wm, wn, lid);
        mma_frag_chunk(acc, (const uint32_t*)(smem + OFF_A2) + c * 32 + 16, 132,
                       (const float4*)(smem + OFF_ACH + buf * 16384 + 8192), wm, wn, lid);
        __syncthreads();
        if (c + 2 < 4) issue_w32(c + 2, buf, sb, tid, Wfrag);
    }
}

// epi1: acc + bias (+G preloaded in A2) -> ELU -> round -> A2; reset acc
template<bool ADDG>
__device__ __forceinline__ void epi1(float (&acc)[2][8][4], char* smem,
                                     int wm, int wn, int lid)
{
    float* A2 = (float*)(smem + OFF_A2);
    const float* be = (const float*)(smem + OFF_BE);
    const int g = lid >> 2, tg = lid & 3;
#pragma unroll
    for (int f = 0; f < 2; f++) {
        int r = wm * 32 + f * 16 + g;
#pragma unroll
        for (int nt = 0; nt < 8; nt++) {
            int n0 = wn * 64 + nt * 8 + tg * 2;
            float be0 = be[n0], be1 = be[n0 + 1];
            float g0x = 0.f, g0y = 0.f, g1x = 0.f, g1y = 0.f;
            if (ADDG) {
                float2 G0 = *(float2*)(A2 + r * 132 + n0);
                float2 G1 = *(float2*)(A2 + (r + 8) * 132 + n0);
                g0x = G0.x; g0y = G0.y; g1x = G1.x; g1y = G1.y;
            }
            float v0 = acc[f][nt][0] + be0 + g0x;
            float v1 = acc[f][nt][1] + be1 + g0y;
            float v2 = acc[f][nt][2] + be0 + g1x;
            float v3 = acc[f][nt][3] + be1 + g1y;
            v0 = (v0 > 0.f) ? v0 : expm1f(v0);
            v1 = (v1 > 0.f) ? v1 : expm1f(v1);
            v2 = (v2 > 0.f) ? v2 : expm1f(v2);
            v3 = (v3 > 0.f) ? v3 : expm1f(v3);
            *(float2*)(A2 + r * 132 + n0)       = make_float2(rtf(v0), rtf(v1));
            *(float2*)(A2 + (r + 8) * 132 + n0) = make_float2(rtf(v2), rtf(v3));
#pragma unroll
            for (int q = 0; q < 4; q++) acc[f][nt][q] = 0.f;
        }
    }
}
// epi2: acc + b2 -> ELU -> (round?) -> A2
template<bool ROUND>
__device__ __forceinline__ void epi2(float (&acc)[2][8][4], char* smem,
                                     int wm, int wn, int lid)
{
    float* A2 = (float*)(smem + OFF_A2);
    const float* be = (const float*)(smem + OFF_B2V);
    const int g = lid >> 2, tg = lid & 3;
#pragma unroll
    for (int f = 0; f < 2; f++) {
        int r = wm * 32 + f * 16 + g;
#pragma unroll
        for (int nt = 0; nt < 8; nt++) {
            int n0 = wn * 64 + nt * 8 + tg * 2;
            float be0 = be[n0], be1 = be[n0 + 1];
            float v0 = acc[f][nt][0] + be0;
            float v1 = acc[f][nt][1] + be1;
            float v2 = acc[f][nt][2] + be0;
            float v3 = acc[f][nt][3] + be1;
            v0 = (v0 > 0.f) ? v0 : expm1f(v0);
            v1 = (v1 > 0.f) ? v1 : expm1f(v1);
            v2 = (v2 > 0.f) ? v2 : expm1f(v2);
            v3 = (v3 > 0.f) ? v3 : expm1f(v3);
            if (ROUND) { v0 = rtf(v0); v1 = rtf(v1); v2 = rtf(v2); v3 = rtf(v3); }
            *(float2*)(A2 + r * 132 + n0)       = make_float2(v0, v1);
            *(float2*)(A2 + (r + 8) * 132 + n0) = make_float2(v2, v3);
        }
    }
}
// store A2 tile to gmem
__device__ __forceinline__ void store_tile(char* smem, float* out, int row0, int tid,
                                           int ostride, int ocol)
{
    const float* A2 = (const float*)(smem + OFF_A2);
#pragma unroll
    for (int i = 0; i < 16; i++) {
        int idx4 = i * 256 + tid;
        int row = idx4 >> 5, c4 = idx4 & 31;
        float4 v = *(const float4*)(A2 + row * 132 + c4 * 4);
        *(float4*)(out + (size_t)(row0 + row) * ostride + ocol + c4 * 4) = v;
    }
}
// BN stats + per-node partial sums from A2 (tid<128: channel tid)
__device__ __forceinline__ void stats_partials(char* smem, int row0, int tid, int bx,
        float* psum, float* psq, float* pnode)
{
    if (tid >= 128) return;
    const float* A2 = (const float*)(smem + OFF_A2);
    float S = 0.f, Q = 0.f, nacc = 0.f;
    int slot = 0;
    int nxt = 23 - (row0 % 23);             // row where a new node starts
    if (nxt == 23 && (row0 % 23) == 0) nxt = 23;  // node starts at r=0: first boundary r=23
    float* pb = pnode + (size_t)bx * 7 * 128;
#pragma unroll 4
    for (int r = 0; r < 128; r++) {
        if (r == nxt) { pb[slot * 128 + tid] = nacc; slot++; nacc = 0.f; nxt += 23; }
        float x = A2[r * 132 + tid];
        S += x; Q += x * x; nacc += x;
    }
    pb[slot * 128 + tid] = nacc;
    psum[(size_t)bx * 128 + tid] = S;
    psq [(size_t)bx * 128 + tid] = Q;
}
// plain stats (node kernels)
__device__ __forceinline__ void stats_only(char* smem, int tid, int bx,
                                           float* psum, float* psq)
{
    if (tid >= 128) return;
    const float* A2 = (const float*)(smem + OFF_A2);
    float S = 0.f, Q = 0.f;
#pragma unroll 8
    for (int r = 0; r < 128; r++) {
        float x = A2[r * 132 + tid];
        S += x; Q += x * x;
    }
    psum[(size_t)bx * 128 + tid] = S;
    psq [(size_t)bx * 128 + tid] = Q;
}
__device__ __forceinline__ void fill_edges(char* smem, int row0, int tid) {
    if (tid < 128) {
        int row = row0 + tid;
        int b = row / NEDGE;
        int e = row - b * NEDGE;
        int r = e / 23;
        int j = e - r * 23;
        int s = j + (j >= r);
        ((int*)(smem + OFF_RECV))[tid] = b * NKPS + r;
        ((int*)(smem + OFF_SEND))[tid] = b * NKPS + s;
    }
}
#define ACC_DECL float acc[2][8][4]; \
    _Pragma("unroll") for (int f_ = 0; f_ < 2; f_++) \
    _Pragma("unroll") for (int n_ = 0; n_ < 8; n_++) \
    _Pragma("unroll") for (int q_ = 0; q_ < 4; q_++) acc[f_][n_][q_] = 0.f;

// =================== kernels ==================================================
__global__ __launch_bounds__(256, 2)
void stage1_mlp(const float* __restrict__ X, const float* __restrict__ W1,
                const float* __restrict__ b1, const float* __restrict__ W2frag,
                const float* __restrict__ b2, float* __restrict__ out,
                float* __restrict__ psum, float* __restrict__ psq)
{
    extern __shared__ char smem[];
    const uint32_t sb = smem_u32(smem);
    const int tid = threadIdx.x, wid = tid >> 5, lid = tid & 31;
    const int wm = wid & 3, wn = wid >> 2;
    const int row0 = blockIdx.x * 128;
    float* smf = (float*)smem;
    if (tid < 128) { smf[OFF_BE/4 + tid] = b1[tid]; smf[OFF_B2V/4 + tid] = b2[tid]; }
#pragma unroll
    for (int i = 0; i < 8; i++) {
        int idx = i * 256 + tid;
        int row = idx >> 4, col = idx & 15;
        float av = (col < 6) ? X[(size_t)(row0 + row) * 6 + col] : 0.f;
        smf[OFF_ACH/4 + row * 20 + col] = rtf(av);
    }
#pragma unroll
    for (int i = 0; i < 8; i++) {
        int o = i * 256 + tid;
        int f4 = o >> 2, reg = o & 3;
        int nb = f4 >> 5, lane = f4 & 31, gg = lane >> 2, tg = lane & 3;
        int n = nb * 8 + gg;
        int k = (reg >> 1) * 8 + (reg & 1) * 4 + tg;
        smf[OFF_WCH/4 + o] = rtf((k < 6) ? W1[n * 6 + k] : 0.f);
    }
    __syncthreads();
    ACC_DECL
    mma_frag_chunk(acc, (const uint32_t*)(smem + OFF_ACH), 20,
                   (const float4*)(smem + OFF_WCH), wm, wn, lid);
    __syncthreads();   // chunk region free before W32 overlay
    epi1<false>(acc, smem, wm, wn, lid);
    __syncthreads();
    layer2_k128(acc, smem, sb, W2frag, wm, wn, lid, tid);
    epi2<true>(acc, smem, wm, wn, lid);
    __syncthreads();
    store_tile(smem, out, row0, tid, 128, 0);
    stats_only(smem, tid, blockIdx.x, psum, psq);
}

__global__ __launch_bounds__(256, 2)
void node_mlp(const float* __restrict__ A, const float* __restrict__ W1frag,
              const float* __restrict__ b1, const float* __restrict__ W2frag,
              const float* __restrict__ b2, float* __restrict__ out,
              float* __restrict__ psum, float* __restrict__ psq)
{
    extern __shared__ char smem[];
    const uint32_t sb = smem_u32(smem);
    const int tid = threadIdx.x, wid = tid >> 5, lid = tid & 31;
    const int wm = wid & 3, wn = wid >> 2;
    const int row0 = blockIdx.x * 128;
    float* smf = (float*)smem;
    if (tid < 128) { smf[OFF_BE/4 + tid] = b1[tid]; smf[OFF_B2V/4 + tid] = b2[tid]; }
    __syncthreads();
    ACC_DECL
    layer_k128(acc, smem, sb, A, row0, W1frag, wm, wn, lid, tid, false);
    epi1<false>(acc, smem, wm, wn, lid);
    __syncthreads();
    layer2_k128(acc, smem, sb, W2frag, wm, wn, lid, tid);
    epi2<true>(acc, smem, wm, wn, lid);
    __syncthreads();
    store_tile(smem, out, row0, tid, 128, 0);
    stats_only(smem, tid, blockIdx.x, psum, psq);
}

// PS[:, blk*128 : +128] = A @ Wfrag(blk)^T, raw fp32
__global__ __launch_bounds__(256, 2)
void gemm_node(const float* __restrict__ A, const float* __restrict__ Wfrag,
               float* __restrict__ PS)
{
    extern __shared__ char smem[];
    const uint32_t sb = smem_u32(smem);
    const int tid = threadIdx.x, wid = tid >> 5, lid = tid & 31;
    const int wm = wid & 3, wn = wid >> 2;
    const int row0 = blockIdx.x * 128;
    const int blk = blockIdx.y;
    ACC_DECL
    layer_k128(acc, smem, sb, A, row0, Wfrag + (size_t)blk * 16384, wm, wn, lid, tid, false);
    float* A2 = (float*)(smem + OFF_A2);
    const int g = lid >> 2, tg = lid & 3;
#pragma unroll
    for (int f = 0; f < 2; f++) {
        int r = wm * 32 + f * 16 + g;
#pragma unroll
        for (int nt = 0; nt < 8; nt++) {
            int n0 = wn * 64 + nt * 8 + tg * 2;
            *(float2*)(A2 + r * 132 + n0)       = make_float2(acc[f][nt][0], acc[f][nt][1]);
            *(float2*)(A2 + (r + 8) * 132 + n0) = make_float2(acc[f][nt][2], acc[f][nt][3]);
        }
    }
    __syncthreads();
    store_tile(smem, PS, row0, tid, 256, blk * 128);
}

// stage 2 edges: A2 = round(ELU(P[recv]+S[send]+beff)); layer2; store h2; stats+partials
__global__ __launch_bounds__(256, 2)
void edge_stage2(const float* __restrict__ PS, const float* __restrict__ beff,
                 const float* __restrict__ W2frag, const float* __restrict__ b2,
                 float* __restrict__ out, float* __restrict__ psum, float* __restrict__ psq,
                 float* __restrict__ pnode)
{
    extern __shared__ char smem[];
    const uint32_t sb = smem_u32(smem);
    const int tid = threadIdx.x, wid = tid >> 5, lid = tid & 31;
    const int wm = wid & 3, wn = wid >> 2;
    const int row0 = blockIdx.x * 128;
    float* smf = (float*)smem;
    fill_edges(smem, row0, tid);
    if (tid < 128) { smf[OFF_BE/4 + tid] = beff[tid]; smf[OFF_B2V/4 + tid] = b2[tid]; }
    __syncthreads();
    const int* rs = (const int*)(smem + OFF_RECV);
    const int* ss = (const int*)(smem + OFF_SEND);
    float* A2 = (float*)(smem + OFF_A2);
    const float* be = smf + OFF_BE/4;
#pragma unroll
    for (int i = 0; i < 16; i++) {
        int idx4 = i * 256 + tid;
        int row = idx4 >> 5, c4 = idx4 & 31;
        float4 p = *(const float4*)(PS + (size_t)rs[row] * 256 + c4 * 4);
        float4 s = *(const float4*)(PS + (size_t)ss[row] * 256 + 128 + c4 * 4);
        float v0 = p.x + s.x + be[c4 * 4];
        float v1 = p.y + s.y + be[c4 * 4 + 1];
        float v2 = p.z + s.z + be[c4 * 4 + 2];
        float v3 = p.w + s.w + be[c4 * 4 + 3];
        v0 = (v0 > 0.f) ? v0 : expm1f(v0);
        v1 = (v1 > 0.f) ? v1 : expm1f(v1);
        v2 = (v2 > 0.f) ? v2 : expm1f(v2);
        v3 = (v3 > 0.f) ? v3 : expm1f(v3);
        *(float4*)(A2 + row * 132 + c4 * 4) = make_float4(rtf(v0), rtf(v1), rtf(v2), rtf(v3));
    }
    ACC_DECL
    layer2_k128(acc, smem, sb, W2frag, wm, wn, lid, tid);
    epi2<true>(acc, smem, wm, wn, lid);
    __syncthreads();
    store_tile(smem, out, row0, tid, 128, 0);
    stats_partials(smem, row0, tid, blockIdx.x, psum, psq, pnode);
}

// stage 4 edges: G = P3[recv]+S3[send] -> A2; skip MMA over H2; epi1 adds G;
// layer2 -> h4 (never stored); stats+partials only
__global__ __launch_bounds__(256, 2)
void edge_stage4(const float* __restrict__ PS3, const float* __restrict__ H2,
                 const float* __restrict__ SKIPfrag, const float* __restrict__ beff,
                 const float* __restrict__ W2frag, const float* __restrict__ b2,
                 float* __restrict__ psum, float* __restrict__ psq,
                 float* __restrict__ pnode)
{
    extern __shared__ char smem[];
    const uint32_t sb = smem_u32(smem);
    const int tid = threadIdx.x, wid = tid >> 5, lid = tid & 31;
    const int wm = wid & 3, wn = wid >> 2;
    const int row0 = blockIdx.x * 128;
    float* smf = (float*)smem;
    fill_edges(smem, row0, tid);
    if (tid < 128) { smf[OFF_BE/4 + tid] = beff[tid]; smf[OFF_B2V/4 + tid] = b2[tid]; }
    issue_aw(0, 0, sb, tid, H2, row0, SKIPfrag);
    issue_aw(1, 1, sb, tid, H2, row0, SKIPfrag);
    __syncthreads();
    const int* rs = (const int*)(smem + OFF_RECV);
    const int* ss = (const int*)(smem + OFF_SEND);
    float* A2 = (float*)(smem + OFF_A2);
#pragma unroll
    for (int i = 0; i < 16; i++) {
        int idx4 = i * 256 + tid;
        int row = idx4 >> 5, c4 = idx4 & 31;
        float4 p = *(const float4*)(PS3 + (size_t)rs[row] * 256 + c4 * 4);
        float4 s = *(const float4*)(PS3 + (size_t)ss[row] * 256 + 128 + c4 * 4);
        *(float4*)(A2 + row * 132 + c4 * 4) =
            make_float4(p.x + s.x, p.y + s.y, p.z + s.z, p.w + s.w);
    }
    ACC_DECL
    layer_k128(acc, smem, sb, H2, row0, SKIPfrag, wm, wn, lid, tid, true);
    epi1<true>(acc, smem, wm, wn, lid);
    __syncthreads();
    layer2_k128(acc, smem, sb, W2frag, wm, wn, lid, tid);
    epi2<false>(acc, smem, wm, wn, lid);
    __syncthreads();
    stats_partials(smem, row0, tid, blockIdx.x, psum, psq, pnode);
}

// combine node partials: each node spans <=2 edge blocks; ascending order
template<bool R>
__global__ void node_combine(const float* __restrict__ pnode,
                             const float* __restrict__ s, const float* __restrict__ t,
                             float* __restrict__ outn)
{
    const int c = threadIdx.x;   // 128
    for (int i = 0; i < 128; i++) {
        int n = blockIdx.x * 128 + i;
        int e0 = n * 23, e1 = e0 + 22;
        int b0 = e0 >> 7, b1 = e1 >> 7;
        int s0 = n - (b0 * 128) / 23;
        float sum = pnode[((size_t)b0 * 7 + s0) * 128 + c];
        if (b1 != b0) {
            int s1 = n - (b1 * 128) / 23;
            sum += pnode[((size_t)b1 * 7 + s1) * 128 + c];
        }
        float val = (s[c] * sum + 23.f * t[c]) * (1.f / 24.f);
        if (R) val = rtf(val);
        outn[(size_t)n * 128 + c] = val;
    }
}

// ---- preps --------------------------------------------------------------------
__global__ void prep_frag(const float* __restrict__ W, int Kin, int kofs,
                          const float* __restrict__ sv, float* __restrict__ dst)
{
    int o = blockIdx.x * 256 + threadIdx.x;
    int c = o >> 11, rem = o & 2047;
    int f4 = rem >> 2, reg = rem & 3;
    int nb = f4 >> 5, lane = f4 & 31;
    int g = lane >> 2, tg = lane & 3;
    int n = nb * 8 + g;
    int k = c * 16 + (reg >> 1) * 8 + (reg & 1) * 4 + tg;
    float v = W[(size_t)n * Kin + kofs + k];
    if (sv) v *= sv[k];
    dst[o] = __uint_as_float(f2tf(v));
}
__global__ void bias_fold(const float* __restrict__ W, int Kin, const float* __restrict__ b,
                          const float* __restrict__ ta, const float* __restrict__ tb,
                          float* __restrict__ beff)
{
    const int n = blockIdx.x, tid = threadIdx.x;
    float partial = 0.f;
    for (int k = tid; k < Kin; k += 128) {
        float t = (k < 256) ? ta[k & 127] : tb[k - 256];
        partial += W[(size_t)n * Kin + k] * t;
    }
    __shared__ float red[128];
    red[tid] = partial;
    __syncthreads();
    for (int off = 64; off; off >>= 1) {
        if (tid < off) red[tid] += red[tid + off];
        __syncthreads();
    }
    if (tid == 0) beff[n] = b[n] + red[0];
}

__global__ void bn_finalize(const float* __restrict__ psum, const float* __restrict__ psq,
                            int nblocks, float Minv,
                            const float* __restrict__ g, const float* __restrict__ be,
                            float* __restrict__ s, float* __restrict__ t)
{
    const int tid = threadIdx.x;
    const int c = tid & 127, part = tid >> 7;
    float S = 0.f, Q = 0.f;
    for (int i = part; i < nblocks; i += 8) {
        S += psum[(size_t)i * 128 + c];
        Q += psq [(size_t)i * 128 + c];
    }
    __shared__ float sS[8][128], sQ[8][128];
    sS[part][c] = S;
    sQ[part][c] = Q;
    __syncthreads();
    if (tid < 128) {
        float St = 0.f, Qt = 0.f;
#pragma unroll
        for (int p = 0; p < 8; p++) { St += sS[p][tid]; Qt += sQ[p][tid]; }
        float mean = St * Minv;
        float var  = Qt * Minv - mean * mean;
        float inv  = rsqrtf(var + BN_EPS);
        float sv   = g[tid] * inv;
        s[tid] = sv;
        t[tid] = be[tid] - mean * sv;
    }
}

__global__ void final_proj(const float* __restrict__ node4,
                           const float* __restrict__ fo_w, const float* __restrict__ fo_b,
                           float* __restrict__ out)
{
    int b = blockIdx.x;
    int c = threadIdx.x;
    float a0 = 0.f, a1 = 0.f;
#pragma unroll
    for (int n = 0; n < NKPS; n++) {
        float v = node4[((size_t)b * NKPS + n) * 128 + c];
        a0 = fmaf(v, fo_w[n * 128 + c],        a0);
        a1 = fmaf(v, fo_w[3072 + n * 128 + c], a1);
    }
    __shared__ float r0[128], r1[128];
    r0[c] = a0; r1[c] = a1;
    __syncthreads();
    for (int off = 64; off; off >>= 1) {
        if (c < off) { r0[c] += r0[c + off]; r1[c] += r1[c + off]; }
        __syncthreads();
    }
    if (c == 0) {
        out[b * 2 + 0] = r0[0] + fo_b[0];
        out[b * 2 + 1] = r1[0] + fo_b[1];
    }
}

// ---- launch -------------------------------------------------------------------
extern "C" void kernel_launch(void* const* d_in, const int* in_sizes, int n_in,
                              void* d_out, int out_size)
{
    const float** I = (const float**)d_in;
    const float* inputs = I[0];
    const float *fo_w = I[3], *fo_b = I[4];
    const float *m1w1 = I[5],  *m1b1 = I[6],  *m1w2 = I[7],  *m1b2 = I[8],  *m1g = I[9],  *m1be = I[10];
    const float *m2w1 = I[11], *m2b1 = I[12], *m2w2 = I[13], *m2b2 = I[14], *m2g = I[15], *m2be = I[16];
    const float *m3w1 = I[17], *m3b1 = I[18], *m3w2 = I[19], *m3b2 = I[20], *m3g = I[21], *m3be = I[22];
    const float *m4w1 = I[23], *m4b1 = I[24], *m4w2 = I[25], *m4b2 = I[26], *m4g = I[27], *m4be = I[28];
    float* out = (float*)d_out;

    float *bufA, *n1, *n2, *n3, *ps, *pnode, *psfrag, *skipfrag, *w1frag, *l2frag;
    float *beff, *psum, *psq, *sA, *tA;
    cudaGetSymbolAddress((void**)&bufA, g_bufA);
    cudaGetSymbolAddress((void**)&n1, g_n1);
    cudaGetSymbolAddress((void**)&n2, g_n2);
    cudaGetSymbolAddress((void**)&n3, g_n3);
    cudaGetSymbolAddress((void**)&ps, g_ps);
    cudaGetSymbolAddress((void**)&pnode, g_pnode);
    cudaGetSymbolAddress((void**)&psfrag, g_psfrag);
    cudaGetSymbolAddress((void**)&skipfrag, g_skipfrag);
    cudaGetSymbolAddress((void**)&w1frag, g_w1frag);
    cudaGetSymbolAddress((void**)&l2frag, g_l2frag);
    cudaGetSymbolAddress((void**)&beff, g_beff);
    cudaGetSymbolAddress((void**)&psum, g_psum);
    cudaGetSymbolAddress((void**)&psq, g_psq);
    cudaGetSymbolAddress((void**)&sA, g_s);
    cudaGetSymbolAddress((void**)&tA, g_t);

    cudaFuncSetAttribute(stage1_mlp,  cudaFuncAttributeMaxDynamicSharedMemorySize, SMEM_TOTAL);
    cudaFuncSetAttribute(node_mlp,    cudaFuncAttributeMaxDynamicSharedMemorySize, SMEM_TOTAL);
    cudaFuncSetAttribute(gemm_node,   cudaFuncAttributeMaxDynamicSharedMemorySize, SMEM_TOTAL);
    cudaFuncSetAttribute(edge_stage2, cudaFuncAttributeMaxDynamicSharedMemorySize, SMEM_TOTAL);
    cudaFuncSetAttribute(edge_stage4, cudaFuncAttributeMaxDynamicSharedMemorySize, SMEM_TOTAL);

    const int GN = M_NODE / 128;   // 192
    const int GE = GE_BLK;         // 4416
    const float MinvN = 1.0f / (float)M_NODE;
    const float MinvE = 1.0f / (float)M_EDGE;
    dim3 gnode(GN, 2);

    // ---- stage 1 ----
    prep_frag<<<64, 256>>>(m1w2, 128, 0, nullptr, l2frag);
    stage1_mlp<<<GN, 256, SMEM_TOTAL>>>(inputs, m1w1, m1b1, l2frag, m1b2, n1, psum, psq);
    bn_finalize<<<1, 1024>>>(psum, psq, GN, MinvN, m1g, m1be, sA + 0, tA + 0);

    // ---- stage 2 ----
    prep_frag<<<64, 256>>>(m2w1, 256, 0,   sA + 0, psfrag);
    prep_frag<<<64, 256>>>(m2w1, 256, 128, sA + 0, psfrag + 16384);
    prep_frag<<<64, 256>>>(m2w2, 128, 0, nullptr, l2frag);
    bias_fold<<<128, 128>>>(m2w1, 256, m2b1, tA + 0, nullptr, beff);
    gemm_node<<<gnode, 256, SMEM_TOTAL>>>(n1, psfrag, ps);
    edge_stage2<<<GE, 256, SMEM_TOTAL>>>(ps, beff, l2frag, m2b2, bufA, psum, psq, pnode);
    bn_finalize<<<1, 1024>>>(psum, psq, GE, MinvE, m2g, m2be, sA + 128, tA + 128);
    node_combine<true><<<GN, 128>>>(pnode, sA + 128, tA + 128, n2);

    // ---- stage 3 ----
    prep_frag<<<64, 256>>>(m3w1, 128, 0, nullptr, w1frag);
    prep_frag<<<64, 256>>>(m3w2, 128, 0, nullptr, l2frag);
    node_mlp<<<GN, 256, SMEM_TOTAL>>>(n2, w1frag, m3b1, l2frag, m3b2, n3, psum, psq);
    bn_finalize<<<1, 1024>>>(psum, psq, GN, MinvN, m3g, m3be, sA + 256, tA + 256);

    // ---- stage 4 ----
    prep_frag<<<64, 256>>>(m4w1, 384, 0,   sA + 256, psfrag);
    prep_frag<<<64, 256>>>(m4w1, 384, 128, sA + 256, psfrag + 16384);
    prep_frag<<<64, 256>>>(m4w1, 384, 256, sA + 128, skipfrag);
    prep_frag<<<64, 256>>>(m4w2, 128, 0, nullptr, l2frag);
    bias_fold<<<128, 128>>>(m4w1, 384, m4b1, tA + 256, tA + 128, beff);
    gemm_node<<<gnode, 256, SMEM_TOTAL>>>(n3, psfrag, ps);
    edge_stage4<<<GE, 256, SMEM_TOTAL>>>(ps, bufA, skipfrag, beff, l2frag, m4b2, psum, psq, pnode);
    bn_finalize<<<1, 1024>>>(psum, psq, GE, MinvE, m4g, m4be, sA + 384, tA + 384);
    node_combine<false><<<GN, 128>>>(pnode, sA + 384, tA + 384, n2);

    final_proj<<<BATCH, 128>>>(n2, fo_w, fo_b, out);
}

// round 9
// speedup vs baseline: 1.3686x; 1.0633x over previous
#include <cuda_runtime.h>
#include <math.h>
#include <stdint.h>

#define BATCH   1024
#define NKPS    24
#define NEDGE   552
#define M_NODE  (BATCH*NKPS)    // 24576
#define M_EDGE  (BATCH*NEDGE)   // 565248
#define GE_BLK  (M_EDGE/128)    // 4416
#define BN_EPS  1e-5f

// ---------------- scratch (device globals) ---------------------------------
__device__ float g_bufA[(size_t)M_EDGE*128];   // h2 (x_skip), tf32-rounded
__device__ float g_n1 [(size_t)M_NODE*128];
__device__ float g_n2 [(size_t)M_NODE*128];
__device__ float g_n3 [(size_t)M_NODE*128];
__device__ float g_ps [(size_t)M_NODE*256];    // P|S per node, fp32
__device__ float g_pnode[(size_t)GE_BLK*7*128];
__device__ float g_psfrag[2*16384];
__device__ float g_skipfrag[16384];
__device__ float g_w1f3[16384];                // stage3 layer1 frags
__device__ float g_l2m1[16384];                // per-stage layer2 frags
__device__ float g_l2m2[16384];
__device__ float g_l2m3[16384];
__device__ float g_l2m4[16384];
__device__ float g_beff[128];
__device__ float g_psum[GE_BLK*128];
__device__ float g_psq [GE_BLK*128];
__device__ float g_s[4*128];
__device__ float g_t[4*128];

// ---------------- helpers ----------------------------------------------------
__device__ __forceinline__ uint32_t smem_u32(const void* p) {
    uint32_t a;
    asm("{ .reg .u64 t; cvta.to.shared.u64 t, %1; cvt.u32.u64 %0, t; }" : "=r"(a) : "l"(p));
    return a;
}
__device__ __forceinline__ void cp16(uint32_t dst, const void* src) {
    asm volatile("cp.async.cg.shared.global [%0], [%1], 16;" :: "r"(dst), "l"(src));
}
__device__ __forceinline__ uint32_t f2tf(float x) {
    uint32_t u;
    asm("cvt.rna.tf32.f32 %0, %1;" : "=r"(u) : "f"(x));
    return u;
}
__device__ __forceinline__ float rtf(float x) { return __uint_as_float(f2tf(x)); }
__device__ __forceinline__ void mma8(float d[4],
                                     uint32_t a0, uint32_t a1, uint32_t a2, uint32_t a3,
                                     uint32_t b0, uint32_t b1) {
    asm volatile("mma.sync.aligned.m16n8k8.row.col.f32.tf32.tf32.f32 "
        "{%0,%1,%2,%3}, {%4,%5,%6,%7}, {%8,%9}, {%0,%1,%2,%3};"
        : "+f"(d[0]), "+f"(d[1]), "+f"(d[2]), "+f"(d[3])
        : "r"(a0), "r"(a1), "r"(a2), "r"(a3), "r"(b0), "r"(b1));
}

// ---------------- SMEM layout (bytes) ----------------------------------------
// Region R (OFF_ACH..OFF_A2): layer-1 A chunks [2x10240] + W16 chunks [2x8192];
// layer-2 overlays W32 chunks [2x16384] at OFF_ACH (safe: layer-1 drained).
#define OFF_RECV   0
#define OFF_SEND   512
#define OFF_BE     1024
#define OFF_B2V    1536
#define OFF_ACH    2048     /* layer-1 A chunks; layer-2 W32 chunks */
#define OFF_WCH    22528    /* layer-1 W16 chunks */
#define OFF_A2     38912    /* 128 x 132 floats = 67584 */
#define SMEM_TOTAL 106496

// ---------------- MMA over one K=16 chunk ------------------------------------
__device__ __forceinline__ void mma_frag_chunk(float (&acc)[2][8][4],
        const uint32_t* As, int AST, const float4* Wc, int wm, int wn, int lid)
{
    const int g = lid >> 2, tg = lid & 3;
    uint32_t a[2][2][4];
#pragma unroll
    for (int f = 0; f < 2; f++) {
        const uint32_t* p = As + (wm * 32 + f * 16 + g) * AST + tg;
#pragma unroll
        for (int ks = 0; ks < 2; ks++) {
            a[f][ks][0] = p[ks * 8];
            a[f][ks][1] = p[8 * AST + ks * 8];
            a[f][ks][2] = p[ks * 8 + 4];
            a[f][ks][3] = p[8 * AST + ks * 8 + 4];
        }
    }
    const float4* wp = Wc + wn * 256 + lid;
#pragma unroll
    for (int nt = 0; nt < 8; nt++) {
        float4 bv = wp[nt * 32];
        uint32_t bx = __float_as_uint(bv.x), by = __float_as_uint(bv.y);
        uint32_t bz = __float_as_uint(bv.z), bw = __float_as_uint(bv.w);
        mma8(acc[0][nt], a[0][0][0], a[0][0][1], a[0][0][2], a[0][0][3], bx, by);
        mma8(acc[1][nt], a[1][0][0], a[1][0][1], a[1][0][2], a[1][0][3], bx, by);
        mma8(acc[0][nt], a[0][1][0], a[0][1][1], a[0][1][2], a[0][1][3], bz, bw);
        mma8(acc[1][nt], a[1][1][0], a[1][1][1], a[1][1][2], a[1][1][3], bz, bw);
    }
}

__device__ __forceinline__ void issue_aw(int c, int buf, uint32_t sb, int tid,
        const float* Asrc, int row0, const float* Wfrag)
{
#pragma unroll
    for (int i = 0; i < 2; i++) {
        int idx4 = i * 256 + tid;
        int row = idx4 >> 2, c4 = idx4 & 3;
        cp16(sb + OFF_ACH + buf * 10240 + row * 80 + c4 * 16,
             Asrc + (size_t)(row0 + row) * 128 + c * 16 + c4 * 4);
    }
#pragma unroll
    for (int i = 0; i < 2; i++) {
        int idx = i * 256 + tid;
        cp16(sb + OFF_WCH + buf * 8192 + idx * 16, Wfrag + c * 2048 + idx * 4);
    }
    asm volatile("cp.async.commit_group;");
}
__device__ __forceinline__ void issue_w32(int c, int buf, uint32_t sb, int tid,
                                          const float* Wfrag)
{
#pragma unroll
    for (int i = 0; i < 4; i++) {
        int idx = i * 256 + tid;
        cp16(sb + OFF_ACH + buf * 16384 + idx * 16, Wfrag + c * 4096 + idx * 4);
    }
    asm volatile("cp.async.commit_group;");
}

// layer-1 over K=128: A rows streamed from gmem, W16 fragment-streamed
__device__ __forceinline__ void layer_k128(float (&acc)[2][8][4], char* smem, uint32_t sb,
        const float* Asrc, int row0, const float* Wfrag,
        int wm, int wn, int lid, int tid, bool preissued)
{
    if (!preissued) {
        issue_aw(0, 0, sb, tid, Asrc, row0, Wfrag);
        issue_aw(1, 1, sb, tid, Asrc, row0, Wfrag);
    }
    for (int c = 0; c < 8; c++) {
        int buf = c & 1;
        if (c < 7) asm volatile("cp.async.wait_group 1;");
        else       asm volatile("cp.async.wait_group 0;");
        __syncthreads();
        mma_frag_chunk(acc, (const uint32_t*)(smem + OFF_ACH + buf * 10240), 20,
                       (const float4*)(smem + OFF_WCH + buf * 8192), wm, wn, lid);
        __syncthreads();
        if (c + 2 < 8) issue_aw(c + 2, buf, sb, tid, Asrc, row0, Wfrag);
    }
}
// layer-2 over K=128: A resident in A2[128][132], W32 fragment-streamed
__device__ __forceinline__ void layer2_k128(float (&acc)[2][8][4], char* smem, uint32_t sb,
        const float* Wfrag, int wm, int wn, int lid, int tid)
{
    issue_w32(0, 0, sb, tid, Wfrag);
    issue_w32(1, 1, sb, tid, Wfrag);
    for (int c = 0; c < 4; c++) {
        int buf = c & 1;
        if (c < 3) asm volatile("cp.async.wait_group 1;");
        else       asm volatile("cp.async.wait_group 0;");
        __syncthreads();
        mma_frag_chunk(acc, (const uint32_t*)(smem + OFF_A2) + c * 32, 132,
                       (const float4*)(smem + OFF_ACH + buf * 16384), wm, wn, lid);
        mma_frag_chunk(acc, (const uint32_t*)(smem + OFF_A2) + c * 32 + 16, 132,
                       (const float4*)(smem + OFF_ACH + buf * 16384 + 8192), wm, wn, lid);
        __syncthreads();
        if (c + 2 < 4) issue_w32(c + 2, buf, sb, tid, Wfrag);
    }
}

// epi1: acc + bias (+G preloaded in A2) -> ELU -> round -> A2; reset acc
template<bool ADDG>
__device__ __forceinline__ void epi1(float (&acc)[2][8][4], char* smem,
                                     int wm, int wn, int lid)
{
    float* A2 = (float*)(smem + OFF_A2);
    const float* be = (const float*)(smem + OFF_BE);
    const int g = lid >> 2, tg = lid & 3;
#pragma unroll
    for (int f = 0; f < 2; f++) {
        int r = wm * 32 + f * 16 + g;
#pragma unroll
        for (int nt = 0; nt < 8; nt++) {
            int n0 = wn * 64 + nt * 8 + tg * 2;
            float be0 = be[n0], be1 = be[n0 + 1];
            float g0x = 0.f, g0y = 0.f, g1x = 0.f, g1y = 0.f;
            if (ADDG) {
                float2 G0 = *(float2*)(A2 + r * 132 + n0);
                float2 G1 = *(float2*)(A2 + (r + 8) * 132 + n0);
                g0x = G0.x; g0y = G0.y; g1x = G1.x; g1y = G1.y;
            }
            float v0 = acc[f][nt][0] + be0 + g0x;
            float v1 = acc[f][nt][1] + be1 + g0y;
            float v2 = acc[f][nt][2] + be0 + g1x;
            float v3 = acc[f][nt][3] + be1 + g1y;
            v0 = (v0 > 0.f) ? v0 : expm1f(v0);
            v1 = (v1 > 0.f) ? v1 : expm1f(v1);
            v2 = (v2 > 0.f) ? v2 : expm1f(v2);
            v3 = (v3 > 0.f) ? v3 : expm1f(v3);
            *(float2*)(A2 + r * 132 + n0)       = make_float2(rtf(v0), rtf(v1));
            *(float2*)(A2 + (r + 8) * 132 + n0) = make_float2(rtf(v2), rtf(v3));
#pragma unroll
            for (int q = 0; q < 4; q++) acc[f][nt][q] = 0.f;
        }
    }
}
// epi2: acc + b2 -> ELU -> (round?) -> A2
template<bool ROUND>
__device__ __forceinline__ void epi2(float (&acc)[2][8][4], char* smem,
                                     int wm, int wn, int lid)
{
    float* A2 = (float*)(smem + OFF_A2);
    const float* be = (const float*)(smem + OFF_B2V);
    const int g = lid >> 2, tg = lid & 3;
#pragma unroll
    for (int f = 0; f < 2; f++) {
        int r = wm * 32 + f * 16 + g;
#pragma unroll
        for (int nt = 0; nt < 8; nt++) {
            int n0 = wn * 64 + nt * 8 + tg * 2;
            float be0 = be[n0], be1 = be[n0 + 1];
            float v0 = acc[f][nt][0] + be0;
            float v1 = acc[f][nt][1] + be1;
            float v2 = acc[f][nt][2] + be0;
            float v3 = acc[f][nt][3] + be1;
            v0 = (v0 > 0.f) ? v0 : expm1f(v0);
            v1 = (v1 > 0.f) ? v1 : expm1f(v1);
            v2 = (v2 > 0.f) ? v2 : expm1f(v2);
            v3 = (v3 > 0.f) ? v3 : expm1f(v3);
            if (ROUND) { v0 = rtf(v0); v1 = rtf(v1); v2 = rtf(v2); v3 = rtf(v3); }
            *(float2*)(A2 + r * 132 + n0)       = make_float2(v0, v1);
            *(float2*)(A2 + (r + 8) * 132 + n0) = make_float2(v2, v3);
        }
    }
}
__device__ __forceinline__ void store_tile(char* smem, float* out, int row0, int tid,
                                           int ostride, int ocol)
{
    const float* A2 = (const float*)(smem + OFF_A2);
#pragma unroll
    for (int i = 0; i < 16; i++) {
        int idx4 = i * 256 + tid;
        int row = idx4 >> 5, c4 = idx4 & 31;
        float4 v = *(const float4*)(A2 + row * 132 + c4 * 4);
        *(float4*)(out + (size_t)(row0 + row) * ostride + ocol + c4 * 4) = v;
    }
}
__device__ __forceinline__ void stats_partials(char* smem, int row0, int tid, int bx,
        float* psum, float* psq, float* pnode)
{
    if (tid >= 128) return;
    const float* A2 = (const float*)(smem + OFF_A2);
    float S = 0.f, Q = 0.f, nacc = 0.f;
    int slot = 0;
    int nxt = 23 - (row0 % 23);
    if (nxt == 23 && (row0 % 23) == 0) nxt = 23;
    float* pb = pnode + (size_t)bx * 7 * 128;
#pragma unroll 4
    for (int r = 0; r < 128; r++) {
        if (r == nxt) { pb[slot * 128 + tid] = nacc; slot++; nacc = 0.f; nxt += 23; }
        float x = A2[r * 132 + tid];
        S += x; Q += x * x; nacc += x;
    }
    pb[slot * 128 + tid] = nacc;
    psum[(size_t)bx * 128 + tid] = S;
    psq [(size_t)bx * 128 + tid] = Q;
}
__device__ __forceinline__ void stats_only(char* smem, int tid, int bx,
                                           float* psum, float* psq)
{
    if (tid >= 128) return;
    const float* A2 = (const float*)(smem + OFF_A2);
    float S = 0.f, Q = 0.f;
#pragma unroll 8
    for (int r = 0; r < 128; r++) {
        float x = A2[r * 132 + tid];
        S += x; Q += x * x;
    }
    psum[(size_t)bx * 128 + tid] = S;
    psq [(size_t)bx * 128 + tid] = Q;
}
__device__ __forceinline__ void fill_edges(char* smem, int row0, int tid) {
    if (tid < 128) {
        int row = row0 + tid;
        int b = row / NEDGE;
        int e = row - b * NEDGE;
        int r = e / 23;
        int j = e - r * 23;
        int s = j + (j >= r);
        ((int*)(smem + OFF_RECV))[tid] = b * NKPS + r;
        ((int*)(smem + OFF_SEND))[tid] = b * NKPS + s;
    }
}
#define ACC_DECL float acc[2][8][4]; \
    _Pragma("unroll") for (int f_ = 0; f_ < 2; f_++) \
    _Pragma("unroll") for (int n_ = 0; n_ < 8; n_++) \
    _Pragma("unroll") for (int q_ = 0; q_ < 4; q_++) acc[f_][n_][q_] = 0.f;

// =================== kernels ==================================================
__global__ __launch_bounds__(256, 2)
void stage1_mlp(const float* __restrict__ X, const float* __restrict__ W1,
                const float* __restrict__ b1, const float* __restrict__ W2frag,
                const float* __restrict__ b2, float* __restrict__ out,
                float* __restrict__ psum, float* __restrict__ psq)
{
    extern __shared__ char smem[];
    const uint32_t sb = smem_u32(smem);
    const int tid = threadIdx.x, wid = tid >> 5, lid = tid & 31;
    const int wm = wid & 3, wn = wid >> 2;
    const int row0 = blockIdx.x * 128;
    float* smf = (float*)smem;
    if (tid < 128) { smf[OFF_BE/4 + tid] = b1[tid]; smf[OFF_B2V/4 + tid] = b2[tid]; }
#pragma unroll
    for (int i = 0; i < 8; i++) {
        int idx = i * 256 + tid;
        int row = idx >> 4, col = idx & 15;
        float av = (col < 6) ? X[(size_t)(row0 + row) * 6 + col] : 0.f;
        smf[OFF_ACH/4 + row * 20 + col] = rtf(av);
    }
#pragma unroll
    for (int i = 0; i < 8; i++) {
        int o = i * 256 + tid;
        int f4 = o >> 2, reg = o & 3;
        int nb = f4 >> 5, lane = f4 & 31, gg = lane >> 2, tg = lane & 3;
        int n = nb * 8 + gg;
        int k = (reg >> 1) * 8 + (reg & 1) * 4 + tg;
        smf[OFF_WCH/4 + o] = rtf((k < 6) ? W1[n * 6 + k] : 0.f);
    }
    __syncthreads();
    ACC_DECL
    mma_frag_chunk(acc, (const uint32_t*)(smem + OFF_ACH), 20,
                   (const float4*)(smem + OFF_WCH), wm, wn, lid);
    __syncthreads();   // chunk region free before W32 overlay
    epi1<false>(acc, smem, wm, wn, lid);
    __syncthreads();
    layer2_k128(acc, smem, sb, W2frag, wm, wn, lid, tid);
    epi2<true>(acc, smem, wm, wn, lid);
    __syncthreads();
    store_tile(smem, out, row0, tid, 128, 0);
    stats_only(smem, tid, blockIdx.x, psum, psq);
}

__global__ __launch_bounds__(256, 2)
void node_mlp(const float* __restrict__ A, const float* __restrict__ W1frag,
              const float* __restrict__ b1, const float* __restrict__ W2frag,
              const float* __restrict__ b2, float* __restrict__ out,
              float* __restrict__ psum, float* __restrict__ psq)
{
    extern __shared__ char smem[];
    const uint32_t sb = smem_u32(smem);
    const int tid = threadIdx.x, wid = tid >> 5, lid = tid & 31;
    const int wm = wid & 3, wn = wid >> 2;
    const int row0 = blockIdx.x * 128;
    float* smf = (float*)smem;
    if (tid < 128) { smf[OFF_BE/4 + tid] = b1[tid]; smf[OFF_B2V/4 + tid] = b2[tid]; }
    __syncthreads();
    ACC_DECL
    layer_k128(acc, smem, sb, A, row0, W1frag, wm, wn, lid, tid, false);
    epi1<false>(acc, smem, wm, wn, lid);
    __syncthreads();
    layer2_k128(acc, smem, sb, W2frag, wm, wn, lid, tid);
    epi2<true>(acc, smem, wm, wn, lid);
    __syncthreads();
    store_tile(smem, out, row0, tid, 128, 0);
    stats_only(smem, tid, blockIdx.x, psum, psq);
}

// PS[:, blk*128 : +128] = A @ Wfrag(blk)^T, raw fp32
__global__ __launch_bounds__(256, 2)
void gemm_node(const float* __restrict__ A, const float* __restrict__ Wfrag,
               float* __restrict__ PS)
{
    extern __shared__ char smem[];
    const uint32_t sb = smem_u32(smem);
    const int tid = threadIdx.x, wid = tid >> 5, lid = tid & 31;
    const int wm = wid & 3, wn = wid >> 2;
    const int row0 = blockIdx.x * 128;
    const int blk = blockIdx.y;
    ACC_DECL
    layer_k128(acc, smem, sb, A, row0, Wfrag + (size_t)blk * 16384, wm, wn, lid, tid, false);
    float* A2 = (float*)(smem + OFF_A2);
    const int g = lid >> 2, tg = lid & 3;
#pragma unroll
    for (int f = 0; f < 2; f++) {
        int r = wm * 32 + f * 16 + g;
#pragma unroll
        for (int nt = 0; nt < 8; nt++) {
            int n0 = wn * 64 + nt * 8 + tg * 2;
            *(float2*)(A2 + r * 132 + n0)       = make_float2(acc[f][nt][0], acc[f][nt][1]);
            *(float2*)(A2 + (r + 8) * 132 + n0) = make_float2(acc[f][nt][2], acc[f][nt][3]);
        }
    }
    __syncthreads();
    store_tile(smem, PS, row0, tid, 256, blk * 128);
}

// stage 2 edges: A2 = round(ELU(P[recv]+S[send]+beff)); layer2; store h2; stats+partials
__global__ __launch_bounds__(256, 2)
void edge_stage2(const float* __restrict__ PS, const float* __restrict__ beff,
                 const float* __restrict__ W2frag, const float* __restrict__ b2,
                 float* __restrict__ out, float* __restrict__ psum, float* __restrict__ psq,
                 float* __restrict__ pnode)
{
    extern __shared__ char smem[];
    const uint32_t sb = smem_u32(smem);
    const int tid = threadIdx.x, wid = tid >> 5, lid = tid & 31;
    const int wm = wid & 3, wn = wid >> 2;
    const int row0 = blockIdx.x * 128;
    float* smf = (float*)smem;
    fill_edges(smem, row0, tid);
    if (tid < 128) { smf[OFF_BE/4 + tid] = beff[tid]; smf[OFF_B2V/4 + tid] = b2[tid]; }
    __syncthreads();
    const int* rs = (const int*)(smem + OFF_RECV);
    const int* ss = (const int*)(smem + OFF_SEND);
    float* A2 = (float*)(smem + OFF_A2);
    const float* be = smf + OFF_BE/4;
#pragma unroll
    for (int i = 0; i < 16; i++) {
        int idx4 = i * 256 + tid;
        int row = idx4 >> 5, c4 = idx4 & 31;
        float4 p = *(const float4*)(PS + (size_t)rs[row] * 256 + c4 * 4);
        float4 s = *(const float4*)(PS + (size_t)ss[row] * 256 + 128 + c4 * 4);
        float v0 = p.x + s.x + be[c4 * 4];
        float v1 = p.y + s.y + be[c4 * 4 + 1];
        float v2 = p.z + s.z + be[c4 * 4 + 2];
        float v3 = p.w + s.w + be[c4 * 4 + 3];
        v0 = (v0 > 0.f) ? v0 : expm1f(v0);
        v1 = (v1 > 0.f) ? v1 : expm1f(v1);
        v2 = (v2 > 0.f) ? v2 : expm1f(v2);
        v3 = (v3 > 0.f) ? v3 : expm1f(v3);
        *(float4*)(A2 + row * 132 + c4 * 4) = make_float4(rtf(v0), rtf(v1), rtf(v2), rtf(v3));
    }
    ACC_DECL
    layer2_k128(acc, smem, sb, W2frag, wm, wn, lid, tid);
    epi2<true>(acc, smem, wm, wn, lid);
    __syncthreads();
    store_tile(smem, out, row0, tid, 128, 0);
    stats_partials(smem, row0, tid, blockIdx.x, psum, psq, pnode);
}

// stage 4 edges: G = P3[recv]+S3[send] -> A2; skip MMA over H2; epi1 adds G;
// layer2 -> h4 (never stored); stats+partials only
__global__ __launch_bounds__(256, 2)
void edge_stage4(const float* __restrict__ PS3, const float* __restrict__ H2,
                 const float* __restrict__ SKIPfrag, const float* __restrict__ beff,
                 const float* __restrict__ W2frag, const float* __restrict__ b2,
                 float* __restrict__ psum, float* __restrict__ psq,
                 float* __restrict__ pnode)
{
    extern __shared__ char smem[];
    const uint32_t sb = smem_u32(smem);
    const int tid = threadIdx.x, wid = tid >> 5, lid = tid & 31;
    const int wm = wid & 3, wn = wid >> 2;
    const int row0 = blockIdx.x * 128;
    float* smf = (float*)smem;
    fill_edges(smem, row0, tid);
    if (tid < 128) { smf[OFF_BE/4 + tid] = beff[tid]; smf[OFF_B2V/4 + tid] = b2[tid]; }
    issue_aw(0, 0, sb, tid, H2, row0, SKIPfrag);
    issue_aw(1, 1, sb, tid, H2, row0, SKIPfrag);
    __syncthreads();
    const int* rs = (const int*)(smem + OFF_RECV);
    const int* ss = (const int*)(smem + OFF_SEND);
    float* A2 = (float*)(smem + OFF_A2);
#pragma unroll
    for (int i = 0; i < 16; i++) {
        int idx4 = i * 256 + tid;
        int row = idx4 >> 5, c4 = idx4 & 31;
        float4 p = *(const float4*)(PS3 + (size_t)rs[row] * 256 + c4 * 4);
        float4 s = *(const float4*)(PS3 + (size_t)ss[row] * 256 + 128 + c4 * 4);
        *(float4*)(A2 + row * 132 + c4 * 4) =
            make_float4(p.x + s.x, p.y + s.y, p.z + s.z, p.w + s.w);
    }
    ACC_DECL
    layer_k128(acc, smem, sb, H2, row0, SKIPfrag, wm, wn, lid, tid, true);
    epi1<true>(acc, smem, wm, wn, lid);
    __syncthreads();
    layer2_k128(acc, smem, sb, W2frag, wm, wn, lid, tid);
    epi2<false>(acc, smem, wm, wn, lid);
    __syncthreads();
    stats_partials(smem, row0, tid, blockIdx.x, psum, psq, pnode);
}

// combine node partials: 1 thread per (node, channel)
template<bool R>
__global__ void node_combine(const float* __restrict__ pnode,
                             const float* __restrict__ s, const float* __restrict__ t,
                             float* __restrict__ outn)
{
    int idx = blockIdx.x * 256 + threadIdx.x;      // M_NODE*128 total
    int n = idx >> 7, c = idx & 127;
    int e0 = n * 23, e1 = e0 + 22;
    int b0 = e0 >> 7, b1 = e1 >> 7;
    int s0 = n - (b0 * 128) / 23;
    float sum = pnode[((size_t)b0 * 7 + s0) * 128 + c];
    if (b1 != b0) {
        int s1 = n - (b1 * 128) / 23;
        sum += pnode[((size_t)b1 * 7 + s1) * 128 + c];
    }
    float val = (s[c] * sum + 23.f * t[c]) * (1.f / 24.f);
    if (R) val = rtf(val);
    outn[(size_t)n * 128 + c] = val;
}

// ---- preps --------------------------------------------------------------------
__device__ __forceinline__ void frag_block(const float* W, int Kin, int kofs,
                                           const float* sv, float* dst, int o)
{
    int c = o >> 11, rem = o & 2047;
    int f4 = rem >> 2, reg = rem & 3;
    int nb = f4 >> 5, lane = f4 & 31;
    int g = lane >> 2, tg = lane & 3;
    int n = nb * 8 + g;
    int k = c * 16 + (reg >> 1) * 8 + (reg & 1) * 4 + tg;
    float v = W[(size_t)n * Kin + kofs + k];
    if (sv) v *= sv[k];
    dst[o] = __uint_as_float(f2tf(v));
}
// bias fold with 256 threads
__device__ __forceinline__ void bias_block(const float* W, int Kin, const float* b,
                                           const float* ta, const float* tb,
                                           float* beff, int n, int tid)
{
    float partial = 0.f;
    for (int k = tid; k < Kin; k += 256) {
        float t = (k < 256) ? ta[k & 127] : tb[k - 256];
        partial += W[(size_t)n * Kin + k] * t;
    }
    __shared__ float red[256];
    red[tid] = partial;
    __syncthreads();
    for (int off = 128; off; off >>= 1) {
        if (tid < off) red[tid] += red[tid + off];
        __syncthreads();
    }
    if (tid == 0) beff[n] = b[n] + red[0];
}

// all scale-independent frags, one launch (grid 320)
__global__ void prep_indep(const float* W0, const float* W1, const float* W2,
                           const float* W3, const float* W4,
                           float* D0, float* D1, float* D2, float* D3, float* D4)
{
    int sel = blockIdx.x >> 6;
    int o = (blockIdx.x & 63) * 256 + threadIdx.x;
    const float* W = (sel == 0) ? W0 : (sel == 1) ? W1 : (sel == 2) ? W2
                   : (sel == 3) ? W3 : W4;
    float* D = (sel == 0) ? D0 : (sel == 1) ? D1 : (sel == 2) ? D2
             : (sel == 3) ? D3 : D4;
    frag_block(W, 128, 0, nullptr, D, o);
}
// stage-2 prep: 2 frag blocks (scaled) + bias fold, one launch (grid 256)
__global__ void prep_stage2(const float* __restrict__ W1, const float* __restrict__ b1,
                            const float* __restrict__ sA, const float* __restrict__ tA,
                            float* __restrict__ psfrag, float* __restrict__ beff)
{
    int bx = blockIdx.x, tid = threadIdx.x;
    if (bx < 64)        frag_block(W1, 256, 0,   sA, psfrag,          (bx       ) * 256 + tid);
    else if (bx < 128)  frag_block(W1, 256, 128, sA, psfrag + 16384,  (bx - 64  ) * 256 + tid);
    else                bias_block(W1, 256, b1, tA, nullptr, beff, bx - 128, tid);
}
// stage-4 prep: 3 frag blocks (scaled) + bias fold, one launch (grid 320)
__global__ void prep_stage4(const float* __restrict__ W1, const float* __restrict__ b1,
                            const float* __restrict__ s3, const float* __restrict__ t3,
                            const float* __restrict__ s2, const float* __restrict__ t2,
                            float* __restrict__ psfrag, float* __restrict__ skipfrag,
                            float* __restrict__ beff)
{
    int bx = blockIdx.x, tid = threadIdx.x;
    if (bx < 64)        frag_block(W1, 384, 0,   s3, psfrag,          (bx       ) * 256 + tid);
    else if (bx < 128)  frag_block(W1, 384, 128, s3, psfrag + 16384,  (bx - 64  ) * 256 + tid);
    else if (bx < 192)  frag_block(W1, 384, 256, s2, skipfrag,        (bx - 128 ) * 256 + tid);
    else                bias_block(W1, 384, b1, t3, t2, beff, bx - 192, tid);
}

__global__ void bn_finalize(const float* __restrict__ psum, const float* __restrict__ psq,
                            int nblocks, float Minv,
                            const float* __restrict__ g, const float* __restrict__ be,
                            float* __restrict__ s, float* __restrict__ t)
{
    const int tid = threadIdx.x;
    const int c = tid & 127, part = tid >> 7;
    float S = 0.f, Q = 0.f;
    for (int i = part; i < nblocks; i += 8) {
        S += psum[(size_t)i * 128 + c];
        Q += psq [(size_t)i * 128 + c];
    }
    __shared__ float sS[8][128], sQ[8][128];
    sS[part][c] = S;
    sQ[part][c] = Q;
    __syncthreads();
    if (tid < 128) {
        float St = 0.f, Qt = 0.f;
#pragma unroll
        for (int p = 0; p < 8; p++) { St += sS[p][tid]; Qt += sQ[p][tid]; }
        float mean = St * Minv;
        float var  = Qt * Minv - mean * mean;
        float inv  = rsqrtf(var + BN_EPS);
        float sv   = g[tid] * inv;
        s[tid] = sv;
        t[tid] = be[tid] - mean * sv;
    }
}

__global__ void final_proj(const float* __restrict__ node4,
                           const float* __restrict__ fo_w, const float* __restrict__ fo_b,
                           float* __restrict__ out)
{
    int b = blockIdx.x;
    int c = threadIdx.x;
    float a0 = 0.f, a1 = 0.f;
#pragma unroll
    for (int n = 0; n < NKPS; n++) {
        float v = node4[((size_t)b * NKPS + n) * 128 + c];
        a0 = fmaf(v, fo_w[n * 128 + c],        a0);
        a1 = fmaf(v, fo_w[3072 + n * 128 + c], a1);
    }
    __shared__ float r0[128], r1[128];
    r0[c] = a0; r1[c] = a1;
    __syncthreads();
    for (int off = 64; off; off >>= 1) {
        if (c < off) { r0[c] += r0[c + off]; r1[c] += r1[c + off]; }
        __syncthreads();
    }
    if (c == 0) {
        out[b * 2 + 0] = r0[0] + fo_b[0];
        out[b * 2 + 1] = r1[0] + fo_b[1];
    }
}

// ---- launch -------------------------------------------------------------------
extern "C" void kernel_launch(void* const* d_in, const int* in_sizes, int n_in,
                              void* d_out, int out_size)
{
    const float** I = (const float**)d_in;
    const float* inputs = I[0];
    const float *fo_w = I[3], *fo_b = I[4];
    const float *m1w1 = I[5],  *m1b1 = I[6],  *m1w2 = I[7],  *m1b2 = I[8],  *m1g = I[9],  *m1be = I[10];
    const float *m2w1 = I[11], *m2b1 = I[12], *m2w2 = I[13], *m2b2 = I[14], *m2g = I[15], *m2be = I[16];
    const float *m3w1 = I[17], *m3b1 = I[18], *m3w2 = I[19], *m3b2 = I[20], *m3g = I[21], *m3be = I[22];
    const float *m4w1 = I[23], *m4b1 = I[24], *m4w2 = I[25], *m4b2 = I[26], *m4g = I[27], *m4be = I[28];
    float* out = (float*)d_out;

    float *bufA, *n1, *n2, *n3, *ps, *pnode, *psfrag, *skipfrag, *w1f3;
    float *l2m1, *l2m2, *l2m3, *l2m4;
    float *beff, *psum, *psq, *sA, *tA;
    cudaGetSymbolAddress((void**)&bufA, g_bufA);
    cudaGetSymbolAddress((void**)&n1, g_n1);
    cudaGetSymbolAddress((void**)&n2, g_n2);
    cudaGetSymbolAddress((void**)&n3, g_n3);
    cudaGetSymbolAddress((void**)&ps, g_ps);
    cudaGetSymbolAddress((void**)&pnode, g_pnode);
    cudaGetSymbolAddress((void**)&psfrag, g_psfrag);
    cudaGetSymbolAddress((void**)&skipfrag, g_skipfrag);
    cudaGetSymbolAddress((void**)&w1f3, g_w1f3);
    cudaGetSymbolAddress((void**)&l2m1, g_l2m1);
    cudaGetSymbolAddress((void**)&l2m2, g_l2m2);
    cudaGetSymbolAddress((void**)&l2m3, g_l2m3);
    cudaGetSymbolAddress((void**)&l2m4, g_l2m4);
    cudaGetSymbolAddress((void**)&beff, g_beff);
    cudaGetSymbolAddress((void**)&psum, g_psum);
    cudaGetSymbolAddress((void**)&psq, g_psq);
    cudaGetSymbolAddress((void**)&sA, g_s);
    cudaGetSymbolAddress((void**)&tA, g_t);

    cudaFuncSetAttribute(stage1_mlp,  cudaFuncAttributeMaxDynamicSharedMemorySize, SMEM_TOTAL);
    cudaFuncSetAttribute(node_mlp,    cudaFuncAttributeMaxDynamicSharedMemorySize, SMEM_TOTAL);
    cudaFuncSetAttribute(gemm_node,   cudaFuncAttributeMaxDynamicSharedMemorySize, SMEM_TOTAL);
    cudaFuncSetAttribute(edge_stage2, cudaFuncAttributeMaxDynamicSharedMemorySize, SMEM_TOTAL);
    cudaFuncSetAttribute(edge_stage4, cudaFuncAttributeMaxDynamicSharedMemorySize, SMEM_TOTAL);

    const int GN = M_NODE / 128;   // 192
    const int GE = GE_BLK;         // 4416
    const float MinvN = 1.0f / (float)M_NODE;
    const float MinvE = 1.0f / (float)M_EDGE;
    dim3 gnode(GN, 2);

    // #1: all scale-independent weight frags
    prep_indep<<<320, 256>>>(m1w2, m2w2, m3w1, m3w2, m4w2,
                             l2m1, l2m2, w1f3, l2m3, l2m4);
    // ---- stage 1 ----
    stage1_mlp<<<GN, 256, SMEM_TOTAL>>>(inputs, m1w1, m1b1, l2m1, m1b2, n1, psum, psq);  // #2
    bn_finalize<<<1, 1024>>>(psum, psq, GN, MinvN, m1g, m1be, sA + 0, tA + 0);           // #3
    // ---- stage 2 ----
    prep_stage2<<<256, 256>>>(m2w1, m2b1, sA + 0, tA + 0, psfrag, beff);                 // #4
    gemm_node<<<gnode, 256, SMEM_TOTAL>>>(n1, psfrag, ps);                               // #5
    edge_stage2<<<GE, 256, SMEM_TOTAL>>>(ps, beff, l2m2, m2b2, bufA, psum, psq, pnode);  // #6 (ncu)
    bn_finalize<<<1, 1024>>>(psum, psq, GE, MinvE, m2g, m2be, sA + 128, tA + 128);
    node_combine<true><<<M_NODE * 128 / 256, 256>>>(pnode, sA + 128, tA + 128, n2);
    // ---- stage 3 ----
    node_mlp<<<GN, 256, SMEM_TOTAL>>>(n2, w1f3, m3b1, l2m3, m3b2, n3, psum, psq);
    bn_finalize<<<1, 1024>>>(psum, psq, GN, MinvN, m3g, m3be, sA + 256, tA + 256);
    // ---- stage 4 ----
    prep_stage4<<<320, 256>>>(m4w1, m4b1, sA + 256, tA + 256, sA + 128, tA + 128,
                              psfrag, skipfrag, beff);
    gemm_node<<<gnode, 256, SMEM_TOTAL>>>(n3, psfrag, ps);
    edge_stage4<<<GE, 256, SMEM_TOTAL>>>(ps, bufA, skipfrag, beff, l2m4, m4b2, psum, psq, pnode);
    bn_finalize<<<1, 1024>>>(psum, psq, GE, MinvE, m4g, m4be, sA + 384, tA + 384);
    node_combine<false><<<M_NODE * 128 / 256, 256>>>(pnode, sA + 384, tA + 384, n2);

    final_proj<<<BATCH, 128>>>(n2, fo_w, fo_b, out);
}

// round 10
// speedup vs baseline: 1.4709x; 1.0748x over previous
#include <cuda_runtime.h>
#include <math.h>
#include <stdint.h>

#define BATCH   1024
#define NKPS    24
#define NEDGE   552
#define M_NODE  (BATCH*NKPS)    // 24576
#define M_EDGE  (BATCH*NEDGE)   // 565248
#define GE_BLK  (M_EDGE/128)    // 4416
#define GN_BLK  (M_NODE/128)    // 192
#define BN_EPS  1e-5f

// ---------------- scratch (device globals) ---------------------------------
__device__ float g_bufA[(size_t)M_EDGE*128];   // h2 (x_skip), tf32-rounded
__device__ float g_n1 [(size_t)M_NODE*128];
__device__ float g_n2 [(size_t)M_NODE*128];
__device__ float g_n3 [(size_t)M_NODE*128];
__device__ float g_ps [(size_t)M_NODE*256];    // P|S per node, fp32
__device__ float g_pnode[(size_t)GE_BLK*7*128];
__device__ float g_psfrag[2*16384];
__device__ float g_skipfrag[16384];
__device__ float g_w1f3[16384];
__device__ float g_l2m1[16384];
__device__ float g_l2m2[16384];
__device__ float g_l2m3[16384];
__device__ float g_l2m4[16384];
__device__ float g_beff[128];
__device__ float g_psum[GE_BLK*128];           // edge: channel-major [128][GE_BLK]; node: block-major
__device__ float g_psq [GE_BLK*128];
__device__ float g_s[4*128];
__device__ float g_t[4*128];

// ---------------- helpers ----------------------------------------------------
__device__ __forceinline__ uint32_t smem_u32(const void* p) {
    uint32_t a;
    asm("{ .reg .u64 t; cvta.to.shared.u64 t, %1; cvt.u32.u64 %0, t; }" : "=r"(a) : "l"(p));
    return a;
}
__device__ __forceinline__ void cp16(uint32_t dst, const void* src) {
    asm volatile("cp.async.cg.shared.global [%0], [%1], 16;" :: "r"(dst), "l"(src));
}
__device__ __forceinline__ uint32_t f2tf(float x) {
    uint32_t u;
    asm("cvt.rna.tf32.f32 %0, %1;" : "=r"(u) : "f"(x));
    return u;
}
__device__ __forceinline__ float rtf(float x) { return __uint_as_float(f2tf(x)); }
__device__ __forceinline__ void mma8(float d[4],
                                     uint32_t a0, uint32_t a1, uint32_t a2, uint32_t a3,
                                     uint32_t b0, uint32_t b1) {
    asm volatile("mma.sync.aligned.m16n8k8.row.col.f32.tf32.tf32.f32 "
        "{%0,%1,%2,%3}, {%4,%5,%6,%7}, {%8,%9}, {%0,%1,%2,%3};"
        : "+f"(d[0]), "+f"(d[1]), "+f"(d[2]), "+f"(d[3])
        : "r"(a0), "r"(a1), "r"(a2), "r"(a3), "r"(b0), "r"(b1));
}

// ---------------- SMEM layout (bytes) ----------------------------------------
#define OFF_RECV   0
#define OFF_SEND   512
#define OFF_BE     1024
#define OFF_B2V    1536
#define OFF_ACH    2048     /* layer-1 A chunks; layer-2 W32 chunks */
#define OFF_WCH    22528    /* layer-1 W16 chunks */
#define OFF_A2     38912    /* 128 x 132 floats = 67584 */
#define SMEM_TOTAL 106496

// ---------------- MMA over one K=16 chunk ------------------------------------
__device__ __forceinline__ void mma_frag_chunk(float (&acc)[2][8][4],
        const uint32_t* As, int AST, const float4* Wc, int wm, int wn, int lid)
{
    const int g = lid >> 2, tg = lid & 3;
    uint32_t a[2][2][4];
#pragma unroll
    for (int f = 0; f < 2; f++) {
        const uint32_t* p = As + (wm * 32 + f * 16 + g) * AST + tg;
#pragma unroll
        for (int ks = 0; ks < 2; ks++) {
            a[f][ks][0] = p[ks * 8];
            a[f][ks][1] = p[8 * AST + ks * 8];
            a[f][ks][2] = p[ks * 8 + 4];
            a[f][ks][3] = p[8 * AST + ks * 8 + 4];
        }
    }
    const float4* wp = Wc + wn * 256 + lid;
#pragma unroll
    for (int nt = 0; nt < 8; nt++) {
        float4 bv = wp[nt * 32];
        uint32_t bx = __float_as_uint(bv.x), by = __float_as_uint(bv.y);
        uint32_t bz = __float_as_uint(bv.z), bw = __float_as_uint(bv.w);
        mma8(acc[0][nt], a[0][0][0], a[0][0][1], a[0][0][2], a[0][0][3], bx, by);
        mma8(acc[1][nt], a[1][0][0], a[1][0][1], a[1][0][2], a[1][0][3], bx, by);
        mma8(acc[0][nt], a[0][1][0], a[0][1][1], a[0][1][2], a[0][1][3], bz, bw);
        mma8(acc[1][nt], a[1][1][0], a[1][1][1], a[1][1][2], a[1][1][3], bz, bw);
    }
}

__device__ __forceinline__ void issue_aw(int c, int buf, uint32_t sb, int tid,
        const float* Asrc, int row0, const float* Wfrag)
{
#pragma unroll
    for (int i = 0; i < 2; i++) {
        int idx4 = i * 256 + tid;
        int row = idx4 >> 2, c4 = idx4 & 3;
        cp16(sb + OFF_ACH + buf * 10240 + row * 80 + c4 * 16,
             Asrc + (size_t)(row0 + row) * 128 + c * 16 + c4 * 4);
    }
#pragma unroll
    for (int i = 0; i < 2; i++) {
        int idx = i * 256 + tid;
        cp16(sb + OFF_WCH + buf * 8192 + idx * 16, Wfrag + c * 2048 + idx * 4);
    }
    asm volatile("cp.async.commit_group;");
}
__device__ __forceinline__ void issue_w32(int c, int buf, uint32_t sb, int tid,
                                          const float* Wfrag)
{
#pragma unroll
    for (int i = 0; i < 4; i++) {
        int idx = i * 256 + tid;
        cp16(sb + OFF_ACH + buf * 16384 + idx * 16, Wfrag + c * 4096 + idx * 4);
    }
    asm volatile("cp.async.commit_group;");
}

// layer-1 over K=128: A rows streamed from gmem, W16 fragment-streamed
__device__ __forceinline__ void layer_k128(float (&acc)[2][8][4], char* smem, uint32_t sb,
        const float* Asrc, int row0, const float* Wfrag,
        int wm, int wn, int lid, int tid, bool preissued)
{
    if (!preissued) {
        issue_aw(0, 0, sb, tid, Asrc, row0, Wfrag);
        issue_aw(1, 1, sb, tid, Asrc, row0, Wfrag);
    }
    for (int c = 0; c < 8; c++) {
        int buf = c & 1;
        if (c < 7) asm volatile("cp.async.wait_group 1;");
        else       asm volatile("cp.async.wait_group 0;");
        __syncthreads();
        mma_frag_chunk(acc, (const uint32_t*)(smem + OFF_ACH + buf * 10240), 20,
                       (const float4*)(smem + OFF_WCH + buf * 8192), wm, wn, lid);
        __syncthreads();
        if (c + 2 < 8) issue_aw(c + 2, buf, sb, tid, Asrc, row0, Wfrag);
    }
}
// layer-2 over K=128: A resident in A2[128][132], W32 fragment-streamed
__device__ __forceinline__ void layer2_k128(float (&acc)[2][8][4], char* smem, uint32_t sb,
        const float* Wfrag, int wm, int wn, int lid, int tid)
{
    issue_w32(0, 0, sb, tid, Wfrag);
    issue_w32(1, 1, sb, tid, Wfrag);
    for (int c = 0; c < 4; c++) {
        int buf = c & 1;
        if (c < 3) asm volatile("cp.async.wait_group 1;");
        else       asm volatile("cp.async.wait_group 0;");
        __syncthreads();
        mma_frag_chunk(acc, (const uint32_t*)(smem + OFF_A2) + c * 32, 132,
                       (const float4*)(smem + OFF_ACH + buf * 16384), wm, wn, lid);
        mma_frag_chunk(acc, (const uint32_t*)(smem + OFF_A2) + c * 32 + 16, 132,
                       (const float4*)(smem + OFF_ACH + buf * 16384 + 8192), wm, wn, lid);
        __syncthreads();
        if (c + 2 < 4) issue_w32(c + 2, buf, sb, tid, Wfrag);
    }
}

// epi1: acc + bias (+G preloaded in A2) -> ELU -> round -> A2; reset acc
template<bool ADDG>
__device__ __forceinline__ void epi1(float (&acc)[2][8][4], char* smem,
                                     int wm, int wn, int lid)
{
    float* A2 = (float*)(smem + OFF_A2);
    const float* be = (const float*)(smem + OFF_BE);
    const int g = lid >> 2, tg = lid & 3;
#pragma unroll
    for (int f = 0; f < 2; f++) {
        int r = wm * 32 + f * 16 + g;
#pragma unroll
        for (int nt = 0; nt < 8; nt++) {
            int n0 = wn * 64 + nt * 8 + tg * 2;
            float be0 = be[n0], be1 = be[n0 + 1];
            float g0x = 0.f, g0y = 0.f, g1x = 0.f, g1y = 0.f;
            if (ADDG) {
                float2 G0 = *(float2*)(A2 + r * 132 + n0);
                float2 G1 = *(float2*)(A2 + (r + 8) * 132 + n0);
                g0x = G0.x; g0y = G0.y; g1x = G1.x; g1y = G1.y;
            }
            float v0 = acc[f][nt][0] + be0 + g0x;
            float v1 = acc[f][nt][1] + be1 + g0y;
            float v2 = acc[f][nt][2] + be0 + g1x;
            float v3 = acc[f][nt][3] + be1 + g1y;
            v0 = (v0 > 0.f) ? v0 : expm1f(v0);
            v1 = (v1 > 0.f) ? v1 : expm1f(v1);
            v2 = (v2 > 0.f) ? v2 : expm1f(v2);
            v3 = (v3 > 0.f) ? v3 : expm1f(v3);
            *(float2*)(A2 + r * 132 + n0)       = make_float2(rtf(v0), rtf(v1));
            *(float2*)(A2 + (r + 8) * 132 + n0) = make_float2(rtf(v2), rtf(v3));
#pragma unroll
            for (int q = 0; q < 4; q++) acc[f][nt][q] = 0.f;
        }
    }
}
// epi2: acc + b2 -> ELU -> (round?) -> A2
template<bool ROUND>
__device__ __forceinline__ void epi2(float (&acc)[2][8][4], char* smem,
                                     int wm, int wn, int lid)
{
    float* A2 = (float*)(smem + OFF_A2);
    const float* be = (const float*)(smem + OFF_B2V);
    const int g = lid >> 2, tg = lid & 3;
#pragma unroll
    for (int f = 0; f < 2; f++) {
        int r = wm * 32 + f * 16 + g;
#pragma unroll
        for (int nt = 0; nt < 8; nt++) {
            int n0 = wn * 64 + nt * 8 + tg * 2;
            float be0 = be[n0], be1 = be[n0 + 1];
            float v0 = acc[f][nt][0] + be0;
            float v1 = acc[f][nt][1] + be1;
            float v2 = acc[f][nt][2] + be0;
            float v3 = acc[f][nt][3] + be1;
            v0 = (v0 > 0.f) ? v0 : expm1f(v0);
            v1 = (v1 > 0.f) ? v1 : expm1f(v1);
            v2 = (v2 > 0.f) ? v2 : expm1f(v2);
            v3 = (v3 > 0.f) ? v3 : expm1f(v3);
            if (ROUND) { v0 = rtf(v0); v1 = rtf(v1); v2 = rtf(v2); v3 = rtf(v3); }
            *(float2*)(A2 + r * 132 + n0)       = make_float2(v0, v1);
            *(float2*)(A2 + (r + 8) * 132 + n0) = make_float2(v2, v3);
        }
    }
}
__device__ __forceinline__ void store_tile(char* smem, float* out, int row0, int tid,
                                           int ostride, int ocol)
{
    const float* A2 = (const float*)(smem + OFF_A2);
#pragma unroll
    for (int i = 0; i < 16; i++) {
        int idx4 = i * 256 + tid;
        int row = idx4 >> 5, c4 = idx4 & 31;
        float4 v = *(const float4*)(A2 + row * 132 + c4 * 4);
        *(float4*)(out + (size_t)(row0 + row) * ostride + ocol + c4 * 4) = v;
    }
}
// edge stats: channel-major psum [128][GE_BLK], plus per-node partials
__device__ __forceinline__ void stats_partials(char* smem, int row0, int tid, int bx,
        float* psum, float* psq, float* pnode)
{
    if (tid >= 128) return;
    const float* A2 = (const float*)(smem + OFF_A2);
    float S = 0.f, Q = 0.f, nacc = 0.f;
    int slot = 0;
    int nxt = 23 - (row0 % 23);
    if (nxt == 23 && (row0 % 23) == 0) nxt = 23;
    float* pb = pnode + (size_t)bx * 7 * 128;
#pragma unroll 4
    for (int r = 0; r < 128; r++) {
        if (r == nxt) { pb[slot * 128 + tid] = nacc; slot++; nacc = 0.f; nxt += 23; }
        float x = A2[r * 132 + tid];
        S += x; Q += x * x; nacc += x;
    }
    pb[slot * 128 + tid] = nacc;
    psum[(size_t)tid * GE_BLK + bx] = S;
    psq [(size_t)tid * GE_BLK + bx] = Q;
}
// node stats: block-major psum [GN][128]
__device__ __forceinline__ void stats_only(char* smem, int tid, int bx,
                                           float* psum, float* psq)
{
    if (tid >= 128) return;
    const float* A2 = (const float*)(smem + OFF_A2);
    float S = 0.f, Q = 0.f;
#pragma unroll 8
    for (int r = 0; r < 128; r++) {
        float x = A2[r * 132 + tid];
        S += x; Q += x * x;
    }
    psum[(size_t)bx * 128 + tid] = S;
    psq [(size_t)bx * 128 + tid] = Q;
}
__device__ __forceinline__ void fill_edges(char* smem, int row0, int tid) {
    if (tid < 128) {
        int row = row0 + tid;
        int b = row / NEDGE;
        int e = row - b * NEDGE;
        int r = e / 23;
        int j = e - r * 23;
        int s = j + (j >= r);
        ((int*)(smem + OFF_RECV))[tid] = b * NKPS + r;
        ((int*)(smem + OFF_SEND))[tid] = b * NKPS + s;
    }
}
#define ACC_DECL float acc[2][8][4]; \
    _Pragma("unroll") for (int f_ = 0; f_ < 2; f_++) \
    _Pragma("unroll") for (int n_ = 0; n_ < 8; n_++) \
    _Pragma("unroll") for (int q_ = 0; q_ < 4; q_++) acc[f_][n_][q_] = 0.f;

// =================== kernels ==================================================
__global__ __launch_bounds__(256, 2)
void stage1_mlp(const float* __restrict__ X, const float* __restrict__ W1,
                const float* __restrict__ b1, const float* __restrict__ W2frag,
                const float* __restrict__ b2, float* __restrict__ out,
                float* __restrict__ psum, float* __restrict__ psq)
{
    extern __shared__ char smem[];
    const uint32_t sb = smem_u32(smem);
    const int tid = threadIdx.x, wid = tid >> 5, lid = tid & 31;
    const int wm = wid & 3, wn = wid >> 2;
    const int row0 = blockIdx.x * 128;
    float* smf = (float*)smem;
    if (tid < 128) { smf[OFF_BE/4 + tid] = b1[tid]; smf[OFF_B2V/4 + tid] = b2[tid]; }
#pragma unroll
    for (int i = 0; i < 8; i++) {
        int idx = i * 256 + tid;
        int row = idx >> 4, col = idx & 15;
        float av = (col < 6) ? X[(size_t)(row0 + row) * 6 + col] : 0.f;
        smf[OFF_ACH/4 + row * 20 + col] = rtf(av);
    }
#pragma unroll
    for (int i = 0; i < 8; i++) {
        int o = i * 256 + tid;
        int f4 = o >> 2, reg = o & 3;
        int nb = f4 >> 5, lane = f4 & 31, gg = lane >> 2, tg = lane & 3;
        int n = nb * 8 + gg;
        int k = (reg >> 1) * 8 + (reg & 1) * 4 + tg;
        smf[OFF_WCH/4 + o] = rtf((k < 6) ? W1[n * 6 + k] : 0.f);
    }
    __syncthreads();
    ACC_DECL
    mma_frag_chunk(acc, (const uint32_t*)(smem + OFF_ACH), 20,
                   (const float4*)(smem + OFF_WCH), wm, wn, lid);
    __syncthreads();
    epi1<false>(acc, smem, wm, wn, lid);
    __syncthreads();
    layer2_k128(acc, smem, sb, W2frag, wm, wn, lid, tid);
    epi2<true>(acc, smem, wm, wn, lid);
    __syncthreads();
    store_tile(smem, out, row0, tid, 128, 0);
    stats_only(smem, tid, blockIdx.x, psum, psq);
}

__global__ __launch_bounds__(256, 2)
void node_mlp(const float* __restrict__ A, const float* __restrict__ W1frag,
              const float* __restrict__ b1, const float* __restrict__ W2frag,
              const float* __restrict__ b2, float* __restrict__ out,
              float* __restrict__ psum, float* __restrict__ psq)
{
    extern __shared__ char smem[];
    const uint32_t sb = smem_u32(smem);
    const int tid = threadIdx.x, wid = tid >> 5, lid = tid & 31;
    const int wm = wid & 3, wn = wid >> 2;
    const int row0 = blockIdx.x * 128;
    float* smf = (float*)smem;
    if (tid < 128) { smf[OFF_BE/4 + tid] = b1[tid]; smf[OFF_B2V/4 + tid] = b2[tid]; }
    __syncthreads();
    ACC_DECL
    layer_k128(acc, smem, sb, A, row0, W1frag, wm, wn, lid, tid, false);
    epi1<false>(acc, smem, wm, wn, lid);
    __syncthreads();
    layer2_k128(acc, smem, sb, W2frag, wm, wn, lid, tid);
    epi2<true>(acc, smem, wm, wn, lid);
    __syncthreads();
    store_tile(smem, out, row0, tid, 128, 0);
    stats_only(smem, tid, blockIdx.x, psum, psq);
}

// PS[:, blk*128 : +128] = A @ Wfrag(blk)^T, raw fp32
__global__ __launch_bounds__(256, 2)
void gemm_node(const float* __restrict__ A, const float* __restrict__ Wfrag,
               float* __restrict__ PS)
{
    extern __shared__ char smem[];
    const uint32_t sb = smem_u32(smem);
    const int tid = threadIdx.x, wid = tid >> 5, lid = tid & 31;
    const int wm = wid & 3, wn = wid >> 2;
    const int row0 = blockIdx.x * 128;
    const int blk = blockIdx.y;
    ACC_DECL
    layer_k128(acc, smem, sb, A, row0, Wfrag + (size_t)blk * 16384, wm, wn, lid, tid, false);
    float* A2 = (float*)(smem + OFF_A2);
    const int g = lid >> 2, tg = lid & 3;
#pragma unroll
    for (int f = 0; f < 2; f++) {
        int r = wm * 32 + f * 16 + g;
#pragma unroll
        for (int nt = 0; nt < 8; nt++) {
            int n0 = wn * 64 + nt * 8 + tg * 2;
            *(float2*)(A2 + r * 132 + n0)       = make_float2(acc[f][nt][0], acc[f][nt][1]);
            *(float2*)(A2 + (r + 8) * 132 + n0) = make_float2(acc[f][nt][2], acc[f][nt][3]);
        }
    }
    __syncthreads();
    store_tile(smem, PS, row0, tid, 256, blk * 128);
}

// stage 2 edges
__global__ __launch_bounds__(256, 2)
void edge_stage2(const float* __restrict__ PS, const float* __restrict__ beff,
                 const float* __restrict__ W2frag, const float* __restrict__ b2,
                 float* __restrict__ out, float* __restrict__ psum, float* __restrict__ psq,
                 float* __restrict__ pnode)
{
    extern __shared__ char smem[];
    const uint32_t sb = smem_u32(smem);
    const int tid = threadIdx.x, wid = tid >> 5, lid = tid & 31;
    const int wm = wid & 3, wn = wid >> 2;
    const int row0 = blockIdx.x * 128;
    float* smf = (float*)smem;
    fill_edges(smem, row0, tid);
    if (tid < 128) { smf[OFF_BE/4 + tid] = beff[tid]; smf[OFF_B2V/4 + tid] = b2[tid]; }
    __syncthreads();
    const int* rs = (const int*)(smem + OFF_RECV);
    const int* ss = (const int*)(smem + OFF_SEND);
    float* A2 = (float*)(smem + OFF_A2);
    const float* be = smf + OFF_BE/4;
#pragma unroll
    for (int i = 0; i < 16; i++) {
        int idx4 = i * 256 + tid;
        int row = idx4 >> 5, c4 = idx4 & 31;
        float4 p = *(const float4*)(PS + (size_t)rs[row] * 256 + c4 * 4);
        float4 s = *(const float4*)(PS + (size_t)ss[row] * 256 + 128 + c4 * 4);
        float v0 = p.x + s.x + be[c4 * 4];
        float v1 = p.y + s.y + be[c4 * 4 + 1];
        float v2 = p.z + s.z + be[c4 * 4 + 2];
        float v3 = p.w + s.w + be[c4 * 4 + 3];
        v0 = (v0 > 0.f) ? v0 : expm1f(v0);
        v1 = (v1 > 0.f) ? v1 : expm1f(v1);
        v2 = (v2 > 0.f) ? v2 : expm1f(v2);
        v3 = (v3 > 0.f) ? v3 : expm1f(v3);
        *(float4*)(A2 + row * 132 + c4 * 4) = make_float4(rtf(v0), rtf(v1), rtf(v2), rtf(v3));
    }
    ACC_DECL
    layer2_k128(acc, smem, sb, W2frag, wm, wn, lid, tid);
    epi2<true>(acc, smem, wm, wn, lid);
    __syncthreads();
    store_tile(smem, out, row0, tid, 128, 0);
    stats_partials(smem, row0, tid, blockIdx.x, psum, psq, pnode);
}

// stage 4 edges
__global__ __launch_bounds__(256, 2)
void edge_stage4(const float* __restrict__ PS3, const float* __restrict__ H2,
                 const float* __restrict__ SKIPfrag, const float* __restrict__ beff,
                 const float* __restrict__ W2frag, const float* __restrict__ b2,
                 float* __restrict__ psum, float* __restrict__ psq,
                 float* __restrict__ pnode)
{
    extern __shared__ char smem[];
    const uint32_t sb = smem_u32(smem);
    const int tid = threadIdx.x, wid = tid >> 5, lid = tid & 31;
    const int wm = wid & 3, wn = wid >> 2;
    const int row0 = blockIdx.x * 128;
    float* smf = (float*)smem;
    fill_edges(smem, row0, tid);
    if (tid < 128) { smf[OFF_BE/4 + tid] = beff[tid]; smf[OFF_B2V/4 + tid] = b2[tid]; }
    issue_aw(0, 0, sb, tid, H2, row0, SKIPfrag);
    issue_aw(1, 1, sb, tid, H2, row0, SKIPfrag);
    __syncthreads();
    const int* rs = (const int*)(smem + OFF_RECV);
    const int* ss = (const int*)(smem + OFF_SEND);
    float* A2 = (float*)(smem + OFF_A2);
#pragma unroll
    for (int i = 0; i < 16; i++) {
        int idx4 = i * 256 + tid;
        int row = idx4 >> 5, c4 = idx4 & 31;
        float4 p = *(const float4*)(PS3 + (size_t)rs[row] * 256 + c4 * 4);
        float4 s = *(const float4*)(PS3 + (size_t)ss[row] * 256 + 128 + c4 * 4);
        *(float4*)(A2 + row * 132 + c4 * 4) =
            make_float4(p.x + s.x, p.y + s.y, p.z + s.z, p.w + s.w);
    }
    ACC_DECL
    layer_k128(acc, smem, sb, H2, row0, SKIPfrag, wm, wn, lid, tid, true);
    epi1<true>(acc, smem, wm, wn, lid);
    __syncthreads();
    layer2_k128(acc, smem, sb, W2frag, wm, wn, lid, tid);
    epi2<false>(acc, smem, wm, wn, lid);
    __syncthreads();
    stats_partials(smem, row0, tid, blockIdx.x, psum, psq, pnode);
}

// combine node partials (stage-2 path): 1 thread per (node, channel)
__global__ void node_combine(const float* __restrict__ pnode,
                             const float* __restrict__ s, const float* __restrict__ t,
                             float* __restrict__ outn)
{
    int idx = blockIdx.x * 256 + threadIdx.x;
    int n = idx >> 7, c = idx & 127;
    int e0 = n * 23, e1 = e0 + 22;
    int b0 = e0 >> 7, b1 = e1 >> 7;
    int s0 = n - (b0 * 128) / 23;
    float sum = pnode[((size_t)b0 * 7 + s0) * 128 + c];
    if (b1 != b0) {
        int s1 = n - (b1 * 128) / 23;
        sum += pnode[((size_t)b1 * 7 + s1) * 128 + c];
    }
    outn[(size_t)n * 128 + c] = rtf((s[c] * sum + 23.f * t[c]) * (1.f / 24.f));
}

// ---- preps --------------------------------------------------------------------
__device__ __forceinline__ void frag_block(const float* W, int Kin, int kofs,
                                           const float* sv, float* dst, int o)
{
    int c = o >> 11, rem = o & 2047;
    int f4 = rem >> 2, reg = rem & 3;
    int nb = f4 >> 5, lane = f4 & 31;
    int g = lane >> 2, tg = lane & 3;
    int n = nb * 8 + g;
    int k = c * 16 + (reg >> 1) * 8 + (reg & 1) * 4 + tg;
    float v = W[(size_t)n * Kin + kofs + k];
    if (sv) v *= sv[k];
    dst[o] = __uint_as_float(f2tf(v));
}
__device__ __forceinline__ void bias_block(const float* W, int Kin, const float* b,
                                           const float* ta, const float* tb,
                                           float* beff, int n, int tid)
{
    float partial = 0.f;
    for (int k = tid; k < Kin; k += 256) {
        float t = (k < 256) ? ta[k & 127] : tb[k - 256];
        partial += W[(size_t)n * Kin + k] * t;
    }
    __shared__ float red[256];
    red[tid] = partial;
    __syncthreads();
    for (int off = 128; off; off >>= 1) {
        if (tid < off) red[tid] += red[tid + off];
        __syncthreads();
    }
    if (tid == 0) beff[n] = b[n] + red[0];
}
// inline BN from block-major node partials [GN_BLK][128] into smem s/t
__device__ __forceinline__ void bn_inline(const float* psum, const float* psq,
                                          float Minv, const float* g, const float* be,
                                          float* ss, float* st, int tid)
{
    if (tid < 128) {
        float S = 0.f, Q = 0.f;
        for (int i = 0; i < GN_BLK; i++) {
            S += psum[i * 128 + tid];
            Q += psq [i * 128 + tid];
        }
        float mean = S * Minv;
        float var  = Q * Minv - mean * mean;
        float inv  = rsqrtf(var + BN_EPS);
        float sv   = g[tid] * inv;
        ss[tid] = sv;
        st[tid] = be[tid] - mean * sv;
    }
    __syncthreads();
}

// all scale-independent frags (grid 320)
__global__ void prep_indep(const float* W0, const float* W1, const float* W2,
                           const float* W3, const float* W4,
                           float* D0, float* D1, float* D2, float* D3, float* D4)
{
    int sel = blockIdx.x >> 6;
    int o = (blockIdx.x & 63) * 256 + threadIdx.x;
    const float* W = (sel == 0) ? W0 : (sel == 1) ? W1 : (sel == 2) ? W2
                   : (sel == 3) ? W3 : W4;
    float* D = (sel == 0) ? D0 : (sel == 1) ? D1 : (sel == 2) ? D2
             : (sel == 3) ? D3 : D4;
    frag_block(W, 128, 0, nullptr, D, o);
}
// stage-2 prep with fused BN1 (grid 256)
__global__ void prep_stage2(const float* __restrict__ W1, const float* __restrict__ b1,
                            const float* __restrict__ psum, const float* __restrict__ psq,
                            float Minv, const float* __restrict__ gg,
                            const float* __restrict__ gb,
                            float* __restrict__ psfrag, float* __restrict__ beff)
{
    __shared__ float ss[128], st[128];
    int bx = blockIdx.x, tid = threadIdx.x;
    bn_inline(psum, psq, Minv, gg, gb, ss, st, tid);
    if (bx < 64)        frag_block(W1, 256, 0,   ss, psfrag,          bx * 256 + tid);
    else if (bx < 128)  frag_block(W1, 256, 128, ss, psfrag + 16384,  (bx - 64) * 256 + tid);
    else                bias_block(W1, 256, b1, st, nullptr, beff, bx - 128, tid);
}
// stage-4 prep with fused BN3 (grid 320); s2/t2 come from bn_edge of stage 2
__global__ void prep_stage4(const float* __restrict__ W1, const float* __restrict__ b1,
                            const float* __restrict__ psum, const float* __restrict__ psq,
                            float Minv, const float* __restrict__ gg,
                            const float* __restrict__ gb,
                            const float* __restrict__ s2, const float* __restrict__ t2,
                            float* __restrict__ psfrag, float* __restrict__ skipfrag,
                            float* __restrict__ beff)
{
    __shared__ float ss[128], st[128];
    int bx = blockIdx.x, tid = threadIdx.x;
    bn_inline(psum, psq, Minv, gg, gb, ss, st, tid);
    if (bx < 64)        frag_block(W1, 384, 0,   ss, psfrag,          bx * 256 + tid);
    else if (bx < 128)  frag_block(W1, 384, 128, ss, psfrag + 16384,  (bx - 64) * 256 + tid);
    else if (bx < 192)  frag_block(W1, 384, 256, s2, skipfrag,        (bx - 128) * 256 + tid);
    else                bias_block(W1, 384, b1, st, t2, beff, bx - 192, tid);
}

// parallel edge BN: channel-major psum [128][GE_BLK], grid 128
__global__ void bn_edge(const float* __restrict__ psum, const float* __restrict__ psq,
                        float Minv, const float* __restrict__ g, const float* __restrict__ be,
                        float* __restrict__ s, float* __restrict__ t)
{
    const int c = blockIdx.x, tid = threadIdx.x;
    float S = 0.f, Q = 0.f;
    for (int i = tid; i < GE_BLK; i += 256) {
        S += psum[(size_t)c * GE_BLK + i];
        Q += psq [(size_t)c * GE_BLK + i];
    }
    __shared__ float rs[256], rq[256];
    rs[tid] = S; rq[tid] = Q;
    __syncthreads();
    for (int off = 128; off; off >>= 1) {
        if (tid < off) { rs[tid] += rs[tid + off]; rq[tid] += rq[tid + off]; }
        __syncthreads();
    }
    if (tid == 0) {
        float mean = rs[0] * Minv;
        float var  = rq[0] * Minv - mean * mean;
        float inv  = rsqrtf(var + BN_EPS);
        float sv   = g[c] * inv;
        s[c] = sv;
        t[c] = be[c] - mean * sv;
    }
}

// final projection with fused node-combine (stage-4 path, fp32)
__global__ void final_proj(const float* __restrict__ pnode,
                           const float* __restrict__ s, const float* __restrict__ t,
                           const float* __restrict__ fo_w, const float* __restrict__ fo_b,
                           float* __restrict__ out)
{
    int b = blockIdx.x;
    int c = threadIdx.x;
    float sc = s[c], tc = t[c];
    float a0 = 0.f, a1 = 0.f;
#pragma unroll
    for (int n = 0; n < NKPS; n++) {
        int nn = b * NKPS + n;
        int e0 = nn * 23, e1 = e0 + 22;
        int b0 = e0 >> 7, b1e = e1 >> 7;
        int s0 = nn - (b0 * 128) / 23;
        float sum = pnode[((size_t)b0 * 7 + s0) * 128 + c];
        if (b1e != b0) {
            int s1 = nn - (b1e * 128) / 23;
            sum += pnode[((size_t)b1e * 7 + s1) * 128 + c];
        }
        float v = (sc * sum + 23.f * tc) * (1.f / 24.f);
        a0 = fmaf(v, fo_w[n * 128 + c],        a0);
        a1 = fmaf(v, fo_w[3072 + n * 128 + c], a1);
    }
    __shared__ float r0[128], r1[128];
    r0[c] = a0; r1[c] = a1;
    __syncthreads();
    for (int off = 64; off; off >>= 1) {
        if (c < off) { r0[c] += r0[c + off]; r1[c] += r1[c + off]; }
        __syncthreads();
    }
    if (c == 0) {
        out[b * 2 + 0] = r0[0] + fo_b[0];
        out[b * 2 + 1] = r1[0] + fo_b[1];
    }
}

// ---- launch -------------------------------------------------------------------
extern "C" void kernel_launch(void* const* d_in, const int* in_sizes, int n_in,
                              void* d_out, int out_size)
{
    const float** I = (const float**)d_in;
    const float* inputs = I[0];
    const float *fo_w = I[3], *fo_b = I[4];
    const float *m1w1 = I[5],  *m1b1 = I[6],  *m1w2 = I[7],  *m1b2 = I[8],  *m1g = I[9],  *m1be = I[10];
    const float *m2w1 = I[11], *m2b1 = I[12], *m2w2 = I[13], *m2b2 = I[14], *m2g = I[15], *m2be = I[16];
    const float *m3w1 = I[17], *m3b1 = I[18], *m3w2 = I[19], *m3b2 = I[20], *m3g = I[21], *m3be = I[22];
    const float *m4w1 = I[23], *m4b1 = I[24], *m4w2 = I[25], *m4b2 = I[26], *m4g = I[27], *m4be = I[28];
    float* out = (float*)d_out;

    float *bufA, *n1, *n2, *n3, *ps, *pnode, *psfrag, *skipfrag, *w1f3;
    float *l2m1, *l2m2, *l2m3, *l2m4;
    float *beff, *psum, *psq, *sA, *tA;
    cudaGetSymbolAddress((void**)&bufA, g_bufA);
    cudaGetSymbolAddress((void**)&n1, g_n1);
    cudaGetSymbolAddress((void**)&n2, g_n2);
    cudaGetSymbolAddress((void**)&n3, g_n3);
    cudaGetSymbolAddress((void**)&ps, g_ps);
    cudaGetSymbolAddress((void**)&pnode, g_pnode);
    cudaGetSymbolAddress((void**)&psfrag, g_psfrag);
    cudaGetSymbolAddress((void**)&skipfrag, g_skipfrag);
    cudaGetSymbolAddress((void**)&w1f3, g_w1f3);
    cudaGetSymbolAddress((void**)&l2m1, g_l2m1);
    cudaGetSymbolAddress((void**)&l2m2, g_l2m2);
    cudaGetSymbolAddress((void**)&l2m3, g_l2m3);
    cudaGetSymbolAddress((void**)&l2m4, g_l2m4);
    cudaGetSymbolAddress((void**)&beff, g_beff);
    cudaGetSymbolAddress((void**)&psum, g_psum);
    cudaGetSymbolAddress((void**)&psq, g_psq);
    cudaGetSymbolAddress((void**)&sA, g_s);
    cudaGetSymbolAddress((void**)&tA, g_t);

    cudaFuncSetAttribute(stage1_mlp,  cudaFuncAttributeMaxDynamicSharedMemorySize, SMEM_TOTAL);
    cudaFuncSetAttribute(node_mlp,    cudaFuncAttributeMaxDynamicSharedMemorySize, SMEM_TOTAL);
    cudaFuncSetAttribute(gemm_node,   cudaFuncAttributeMaxDynamicSharedMemorySize, SMEM_TOTAL);
    cudaFuncSetAttribute(edge_stage2, cudaFuncAttributeMaxDynamicSharedMemorySize, SMEM_TOTAL);
    cudaFuncSetAttribute(edge_stage4, cudaFuncAttributeMaxDynamicSharedMemorySize, SMEM_TOTAL);

    const int GN = GN_BLK;         // 192
    const int GE = GE_BLK;         // 4416
    const float MinvN = 1.0f / (float)M_NODE;
    const float MinvE = 1.0f / (float)M_EDGE;
    dim3 gnode(GN, 2);

    // #1: all scale-independent weight frags
    prep_indep<<<320, 256>>>(m1w2, m2w2, m3w1, m3w2, m4w2,
                             l2m1, l2m2, w1f3, l2m3, l2m4);
    // #2: stage 1
    stage1_mlp<<<GN, 256, SMEM_TOTAL>>>(inputs, m1w1, m1b1, l2m1, m1b2, n1, psum, psq);
    // #3: stage-2 prep (BN1 fused)
    prep_stage2<<<256, 256>>>(m2w1, m2b1, psum, psq, MinvN, m1g, m1be, psfrag, beff);
    // #4: node P/S GEMM  <-- profiled launch
    gemm_node<<<gnode, 256, SMEM_TOTAL>>>(n1, psfrag, ps);
    // #5: edges stage 2
    edge_stage2<<<GE, 256, SMEM_TOTAL>>>(ps, beff, l2m2, m2b2, bufA, psum, psq, pnode);
    // #6: BN2 (parallel)
    bn_edge<<<128, 256>>>(psum, psq, MinvE, m2g, m2be, sA + 128, tA + 128);
    // #7: edge2node
    node_combine<<<M_NODE * 128 / 256, 256>>>(pnode, sA + 128, tA + 128, n2);
    // #8: stage 3
    node_mlp<<<GN, 256, SMEM_TOTAL>>>(n2, w1f3, m3b1, l2m3, m3b2, n3, psum, psq);
    // #9: stage-4 prep (BN3 fused)
    prep_stage4<<<320, 256>>>(m4w1, m4b1, psum, psq, MinvN, m3g, m3be,
                              sA + 128, tA + 128, psfrag, skipfrag, beff);
    // #10: node P/S GEMM for stage 4
    gemm_node<<<gnode, 256, SMEM_TOTAL>>>(n3, psfrag, ps);
    // #11: edges stage 4
    edge_stage4<<<GE, 256, SMEM_TOTAL>>>(ps, bufA, skipfrag, beff, l2m4, m4b2, psum, psq, pnode);
    // #12: BN4 (parallel)
    bn_edge<<<128, 256>>>(psum, psq, MinvE, m4g, m4be, sA + 384, tA + 384);
    // #13: final projection with fused combine
    final_proj<<<BATCH, 128>>>(pnode, sA + 384, tA + 384, fo_w, fo_b, out);
}